// round 1
// baseline (speedup 1.0000x reference)
#include <cuda_runtime.h>
#include <math.h>

// ---------------------------------------------------------------------------
// ViT forward, fp32 baseline. B=32, L=6, E=768, H=8, HD=96, N=197 tokens.
// ---------------------------------------------------------------------------

namespace {
constexpr int B_   = 32;
constexpr int C_   = 3;
constexpr int IMG_ = 224;
constexpr int P_   = 16;
constexpr int E_   = 768;
constexpr int H_   = 8;
constexpr int L_   = 6;
constexpr int NC_  = 1000;
constexpr int HD_  = 96;          // E/H
constexpr int NP_  = 196;         // (IMG/P)^2
constexpr int N_   = 197;         // NP + cls
constexpr int M_   = B_ * N_;     // 6304 token rows
constexpr int MP_  = B_ * NP_;    // 6272 patch rows
constexpr int FF_  = 4 * E_;      // 3072
constexpr float SCALE_ = 0.1020620726159657f;  // HD^-0.5
constexpr float EPS_   = 1e-5f;

// scratch pool layout (floats)
constexpr size_t oX     = 0;
constexpr size_t oPATCH = oX     + (size_t)M_ * E_;
constexpr size_t oPE    = oPATCH + (size_t)MP_ * E_;
constexpr size_t oQKV   = oPE    + (size_t)MP_ * E_;
constexpr size_t oATT   = oQKV   + (size_t)M_ * 3 * E_;
constexpr size_t oHID   = oATT   + (size_t)M_ * E_;
constexpr size_t oT2    = oHID   + (size_t)M_ * FF_;
constexpr size_t oPOOL  = oT2    + (size_t)M_ * E_;
constexpr size_t oPOOLN = oPOOL  + (size_t)B_ * E_;
constexpr size_t TOT    = oPOOLN + (size_t)B_ * E_;
}  // namespace

__device__ float g_pool[TOT];

// ---------------------------------------------------------------------------
// helpers
// ---------------------------------------------------------------------------
__device__ __forceinline__ float gelu_f(float x) {
    return 0.5f * x * (1.f + erff(x * 0.7071067811865475f));
}

// ---------------------------------------------------------------------------
// im2col: x[B,C,224,224] -> patch[MP, 768] with col = c*256 + i*16 + j
// ---------------------------------------------------------------------------
__global__ void k_im2col(const float* __restrict__ x, float* __restrict__ patch) {
    int idx = blockIdx.x * 256 + threadIdx.x;
    if (idx >= MP_ * E_) return;
    int row = idx / E_;
    int k   = idx - row * E_;
    int b   = row / NP_;
    int p   = row - b * NP_;
    int hp  = p / 14, wp = p - hp * 14;
    int c   = k >> 8;          // /256
    int i   = (k >> 4) & 15;
    int j   = k & 15;
    patch[idx] = x[((size_t)(b * C_ + c) * IMG_ + hp * P_ + i) * IMG_ + wp * P_ + j];
}

// ---------------------------------------------------------------------------
// assemble: X[b,0,:] = cls + pos[0]; X[b,t,:] = PE[b,t-1,:] + pos[t]
// ---------------------------------------------------------------------------
__global__ void k_assemble(const float* __restrict__ pe, const float* __restrict__ cls,
                           const float* __restrict__ pos, float* __restrict__ X) {
    int idx = blockIdx.x * 256 + threadIdx.x;
    if (idx >= M_ * E_) return;
    int row = idx / E_;
    int e   = idx - row * E_;
    int b   = row / N_;
    int t   = row - b * N_;
    float v;
    if (t == 0) v = cls[e] + pos[e];
    else        v = pe[(size_t)(b * NP_ + (t - 1)) * E_ + e] + pos[(size_t)t * E_ + e];
    X[idx] = v;
}

// ---------------------------------------------------------------------------
// SGEMM (TN, both operands K-contiguous): C[M,N] = A[M,K] * B[N,K]^T + bias
// BM=BN=128, BK=8, 256 threads, 8x8 microtile. act: 0 none, 1 exact GELU.
// ---------------------------------------------------------------------------
__global__ void k_sgemm(const float* __restrict__ A, const float* __restrict__ Bw,
                        const float* __restrict__ bias, float* __restrict__ C,
                        int M, int N, int K, int act) {
    __shared__ float As[8][128];
    __shared__ float Bs[8][128];
    const int tid  = threadIdx.x;
    const int row0 = blockIdx.y * 128;
    const int col0 = blockIdx.x * 128;
    const int lr   = tid >> 1;           // 0..127
    const int lk   = (tid & 1) * 4;      // 0 or 4
    const int ty   = tid >> 4;           // 0..15
    const int tx   = tid & 15;           // 0..15

    float acc[8][8];
#pragma unroll
    for (int i = 0; i < 8; i++)
#pragma unroll
        for (int j = 0; j < 8; j++) acc[i][j] = 0.f;

    const bool aval = (row0 + lr) < M;
    const bool bval = (col0 + lr) < N;
    const float* Ap = A  + (size_t)(row0 + lr) * K + lk;
    const float* Bp = Bw + (size_t)(col0 + lr) * K + lk;

    for (int k0 = 0; k0 < K; k0 += 8) {
        float4 a4 = aval ? *(const float4*)(Ap + k0) : make_float4(0.f, 0.f, 0.f, 0.f);
        float4 b4 = bval ? *(const float4*)(Bp + k0) : make_float4(0.f, 0.f, 0.f, 0.f);
        As[lk + 0][lr] = a4.x; As[lk + 1][lr] = a4.y;
        As[lk + 2][lr] = a4.z; As[lk + 3][lr] = a4.w;
        Bs[lk + 0][lr] = b4.x; Bs[lk + 1][lr] = b4.y;
        Bs[lk + 2][lr] = b4.z; Bs[lk + 3][lr] = b4.w;
        __syncthreads();
#pragma unroll
        for (int kk = 0; kk < 8; kk++) {
            float ar[8], br[8];
#pragma unroll
            for (int i = 0; i < 8; i++) ar[i] = As[kk][ty * 8 + i];
#pragma unroll
            for (int j = 0; j < 8; j++) br[j] = Bs[kk][tx * 8 + j];
#pragma unroll
            for (int i = 0; i < 8; i++)
#pragma unroll
                for (int j = 0; j < 8; j++) acc[i][j] += ar[i] * br[j];
        }
        __syncthreads();
    }

#pragma unroll
    for (int i = 0; i < 8; i++) {
        int r = row0 + ty * 8 + i;
        if (r >= M) continue;
        float* cr = C + (size_t)r * N;
#pragma unroll
        for (int j = 0; j < 8; j++) {
            int c = col0 + tx * 8 + j;
            if (c >= N) continue;
            float v = acc[i][j];
            if (bias) v += bias[c];
            if (act) v = gelu_f(v);
            cr[c] = v;
        }
    }
}

// ---------------------------------------------------------------------------
// Fused attention: one block per (b, head). K,V staged in smem (stride 97 to
// avoid 96%32==0 bank conflicts). softmax over keys, then * SCALE (faithful).
// ---------------------------------------------------------------------------
__global__ void k_attn(const float* __restrict__ QKV, float* __restrict__ OUT) {
    const int b = blockIdx.x >> 3;
    const int h = blockIdx.x & 7;
    extern __shared__ float sm[];
    float* Ks = sm;                       // [197*97]
    float* Vs = Ks + N_ * 97;             // [197*97]
    float* Ps = Vs + N_ * 97;             // [8*197]
    float* Qs = Ps + 8 * N_;              // [8*96]

    const float* base = QKV + (size_t)b * N_ * (3 * E_);
    const int tid = threadIdx.x;

    for (int idx = tid; idx < N_ * HD_; idx += 256) {
        int t = idx / HD_, d = idx - t * HD_;
        const float* rp = base + (size_t)t * (3 * E_) + h * HD_;
        Ks[t * 97 + d] = rp[E_ + d];
        Vs[t * 97 + d] = rp[2 * E_ + d];
    }
    __syncthreads();

    const int warp = tid >> 5, lane = tid & 31;
    int jcl[7];
#pragma unroll
    for (int jj = 0; jj < 7; jj++) {
        int j = jj * 32 + lane;
        jcl[jj] = (j < N_ ? j : N_ - 1) * 97;
    }

    for (int q = warp; q < N_; q += 8) {
        const float* qp = base + (size_t)(q) * (3 * E_) + h * HD_;
        Qs[warp * HD_ + lane]      = qp[lane];
        Qs[warp * HD_ + lane + 32] = qp[lane + 32];
        Qs[warp * HD_ + lane + 64] = qp[lane + 64];
        __syncwarp();

        float s[7];
#pragma unroll
        for (int jj = 0; jj < 7; jj++) s[jj] = 0.f;
#pragma unroll 4
        for (int d = 0; d < HD_; d++) {
            float qd = Qs[warp * HD_ + d];
#pragma unroll
            for (int jj = 0; jj < 7; jj++) s[jj] += qd * Ks[jcl[jj] + d];
        }

        float mx = -1e30f;
#pragma unroll
        for (int jj = 0; jj < 7; jj++)
            if (jj * 32 + lane < N_) mx = fmaxf(mx, s[jj]);
#pragma unroll
        for (int o = 16; o > 0; o >>= 1)
            mx = fmaxf(mx, __shfl_xor_sync(0xffffffffu, mx, o));

        float sum = 0.f;
#pragma unroll
        for (int jj = 0; jj < 7; jj++) {
            float e = (jj * 32 + lane < N_) ? __expf(s[jj] - mx) : 0.f;
            s[jj] = e;
            sum += e;
        }
#pragma unroll
        for (int o = 16; o > 0; o >>= 1)
            sum += __shfl_xor_sync(0xffffffffu, sum, o);

        const float inv = SCALE_ / sum;   // softmax then *SCALE
#pragma unroll
        for (int jj = 0; jj < 7; jj++) {
            int j = jj * 32 + lane;
            if (j < N_) Ps[warp * N_ + j] = s[jj] * inv;
        }
        __syncwarp();

        float a0 = 0.f, a1 = 0.f, a2 = 0.f;
        for (int j = 0; j < N_; j++) {
            float p = Ps[warp * N_ + j];
            const float* vr = Vs + j * 97;
            a0 += p * vr[lane];
            a1 += p * vr[lane + 32];
            a2 += p * vr[lane + 64];
        }
        float* op = OUT + ((size_t)(b * N_ + q)) * E_ + h * HD_;
        op[lane]      = a0;
        op[lane + 32] = a1;
        op[lane + 64] = a2;
        __syncwarp();
    }
}

// ---------------------------------------------------------------------------
// add + LayerNorm per row of E_=768 (R may be nullptr => plain LN).
// In-place safe (reads complete before writes).
// ---------------------------------------------------------------------------
__global__ void k_add_ln(const float* __restrict__ Xin, const float* __restrict__ R,
                         float* __restrict__ Xout, const float* __restrict__ g,
                         const float* __restrict__ bt) {
    const int row = blockIdx.x;
    const int tid = threadIdx.x;
    const float* xr = Xin + (size_t)row * E_;
    const float* rr = R ? R + (size_t)row * E_ : nullptr;

    float v[3];
    float sum = 0.f, sq = 0.f;
#pragma unroll
    for (int c = 0; c < 3; c++) {
        int e = tid + c * 256;
        float t = xr[e] + (rr ? rr[e] : 0.f);
        v[c] = t;
        sum += t;
        sq += t * t;
    }
#pragma unroll
    for (int o = 16; o > 0; o >>= 1) {
        sum += __shfl_xor_sync(0xffffffffu, sum, o);
        sq  += __shfl_xor_sync(0xffffffffu, sq, o);
    }
    __shared__ float rs[8], rq[8];
    const int warp = tid >> 5, lane = tid & 31;
    if (lane == 0) { rs[warp] = sum; rq[warp] = sq; }
    __syncthreads();
    sum = 0.f; sq = 0.f;
#pragma unroll
    for (int w = 0; w < 8; w++) { sum += rs[w]; sq += rq[w]; }

    const float m   = sum * (1.f / E_);
    const float var = sq * (1.f / E_) - m * m;
    const float inv = rsqrtf(var + EPS_);
    float* orow = Xout + (size_t)row * E_;
#pragma unroll
    for (int c = 0; c < 3; c++) {
        int e = tid + c * 256;
        orow[e] = (v[c] - m) * inv * g[e] + bt[e];
    }
}

// ---------------------------------------------------------------------------
// mean pool over tokens
// ---------------------------------------------------------------------------
__global__ void k_pool(const float* __restrict__ X, float* __restrict__ P) {
    const int b = blockIdx.x / 3;
    const int e = (blockIdx.x % 3) * 256 + threadIdx.x;
    const float* xp = X + (size_t)b * N_ * E_ + e;
    float s = 0.f;
    for (int t = 0; t < N_; t++) s += xp[(size_t)t * E_];
    P[b * E_ + e] = s * (1.f / N_);
}

// ---------------------------------------------------------------------------
// host
// ---------------------------------------------------------------------------
extern "C" void kernel_launch(void* const* d_in, const int* in_sizes, int n_in,
                              void* d_out, int out_size) {
    const float* x      = (const float*)d_in[0];
    const float* conv_w = (const float*)d_in[1];
    const float* conv_b = (const float*)d_in[2];
    const float* cls    = (const float*)d_in[3];
    const float* pos    = (const float*)d_in[4];
    const float* qkv_w  = (const float*)d_in[5];
    const float* qkv_b  = (const float*)d_in[6];
    const float* proj_w = (const float*)d_in[7];
    const float* proj_b = (const float*)d_in[8];
    const float* ln1_g  = (const float*)d_in[9];
    const float* ln1_b  = (const float*)d_in[10];
    const float* mlp_w1 = (const float*)d_in[11];
    const float* mlp_b1 = (const float*)d_in[12];
    const float* mlp_w2 = (const float*)d_in[13];
    const float* mlp_b2 = (const float*)d_in[14];
    const float* ln2_g  = (const float*)d_in[15];
    const float* ln2_b  = (const float*)d_in[16];
    const float* hln_g  = (const float*)d_in[17];
    const float* hln_b  = (const float*)d_in[18];
    const float* head_w = (const float*)d_in[19];
    const float* head_b = (const float*)d_in[20];
    float* out = (float*)d_out;

    float* pool = nullptr;
    cudaGetSymbolAddress((void**)&pool, g_pool);
    float* X     = pool + oX;
    float* PATCH = pool + oPATCH;
    float* PE    = pool + oPE;
    float* QKV   = pool + oQKV;
    float* ATT   = pool + oATT;
    float* HID   = pool + oHID;
    float* T2    = pool + oT2;
    float* POOL  = pool + oPOOL;
    float* POOLN = pool + oPOOLN;

    const int attn_smem = (int)((2 * N_ * 97 + 8 * N_ + 8 * HD_) * sizeof(float));
    cudaFuncSetAttribute(k_attn, cudaFuncAttributeMaxDynamicSharedMemorySize, attn_smem);

    // patch embed
    k_im2col<<<(MP_ * E_ + 255) / 256, 256>>>(x, PATCH);
    {
        dim3 g((E_ + 127) / 128, (MP_ + 127) / 128);
        k_sgemm<<<g, 256>>>(PATCH, conv_w, conv_b, PE, MP_, E_, E_, 0);
    }
    k_assemble<<<(M_ * E_ + 255) / 256, 256>>>(PE, cls, pos, X);

    for (int l = 0; l < L_; l++) {
        const float* qw  = qkv_w  + (size_t)l * 3 * E_ * E_;
        const float* qb  = qkv_b  + (size_t)l * 3 * E_;
        const float* pw  = proj_w + (size_t)l * E_ * E_;
        const float* pb  = proj_b + (size_t)l * E_;
        const float* g1g = ln1_g  + (size_t)l * E_;
        const float* g1b = ln1_b  + (size_t)l * E_;
        const float* w1  = mlp_w1 + (size_t)l * FF_ * E_;
        const float* b1  = mlp_b1 + (size_t)l * FF_;
        const float* w2  = mlp_w2 + (size_t)l * E_ * FF_;
        const float* b2  = mlp_b2 + (size_t)l * E_;
        const float* g2g = ln2_g  + (size_t)l * E_;
        const float* g2b = ln2_b  + (size_t)l * E_;

        {
            dim3 g((3 * E_ + 127) / 128, (M_ + 127) / 128);
            k_sgemm<<<g, 256>>>(X, qw, qb, QKV, M_, 3 * E_, E_, 0);
        }
        k_attn<<<B_ * H_, 256, attn_smem>>>(QKV, ATT);
        {
            dim3 g((E_ + 127) / 128, (M_ + 127) / 128);
            k_sgemm<<<g, 256>>>(ATT, pw, pb, T2, M_, E_, E_, 0);
        }
        k_add_ln<<<M_, 256>>>(X, T2, X, g1g, g1b);
        {
            dim3 g((FF_ + 127) / 128, (M_ + 127) / 128);
            k_sgemm<<<g, 256>>>(X, w1, b1, HID, M_, FF_, E_, 1);
        }
        {
            dim3 g((E_ + 127) / 128, (M_ + 127) / 128);
            k_sgemm<<<g, 256>>>(HID, w2, b2, T2, M_, E_, FF_, 0);
        }
        k_add_ln<<<M_, 256>>>(X, T2, X, g2g, g2b);
    }

    // classifier head
    k_pool<<<B_ * 3, 256>>>(X, POOL);
    k_add_ln<<<B_, 256>>>(POOL, nullptr, POOLN, hln_g, hln_b);
    {
        dim3 g((NC_ + 127) / 128, (B_ + 127) / 128);
        k_sgemm<<<g, 256>>>(POOLN, head_w, head_b, out, B_, NC_, E_, 0);
    }
}

// round 2
// speedup vs baseline: 2.0701x; 2.0701x over previous
#include <cuda_runtime.h>
#include <math.h>

// ---------------------------------------------------------------------------
// ViT forward. B=32, L=6, E=768, H=8, HD=96, N=197 tokens.
// Round 2: TF32 mma.sync GEMMs (fp32 accumulate), fused attention fp32.
// ---------------------------------------------------------------------------

namespace {
constexpr int B_   = 32;
constexpr int C_   = 3;
constexpr int IMG_ = 224;
constexpr int P_   = 16;
constexpr int E_   = 768;
constexpr int H_   = 8;
constexpr int L_   = 6;
constexpr int NC_  = 1000;
constexpr int HD_  = 96;          // E/H
constexpr int NP_  = 196;         // (IMG/P)^2
constexpr int N_   = 197;         // NP + cls
constexpr int M_   = B_ * N_;     // 6304 token rows
constexpr int MP_  = B_ * NP_;    // 6272 patch rows
constexpr int FF_  = 4 * E_;      // 3072
constexpr float SCALE_ = 0.1020620726159657f;  // HD^-0.5
constexpr float EPS_   = 1e-5f;

// scratch pool layout (floats)
constexpr size_t oX     = 0;
constexpr size_t oPATCH = oX     + (size_t)M_ * E_;
constexpr size_t oPE    = oPATCH + (size_t)MP_ * E_;
constexpr size_t oQKV   = oPE    + (size_t)MP_ * E_;
constexpr size_t oATT   = oQKV   + (size_t)M_ * 3 * E_;
constexpr size_t oHID   = oATT   + (size_t)M_ * E_;
constexpr size_t oT2    = oHID   + (size_t)M_ * FF_;
constexpr size_t oPOOL  = oT2    + (size_t)M_ * E_;
constexpr size_t oPOOLN = oPOOL  + (size_t)B_ * E_;
constexpr size_t TOT    = oPOOLN + (size_t)B_ * E_;
}  // namespace

__device__ float g_pool[TOT];

// ---------------------------------------------------------------------------
// helpers
// ---------------------------------------------------------------------------
__device__ __forceinline__ float gelu_f(float x) {
    return 0.5f * x * (1.f + erff(x * 0.7071067811865475f));
}

__device__ __forceinline__ float to_tf32(float x) {
    asm("cvt.rna.tf32.f32 %0, %0;" : "+f"(x));
    return x;
}

__device__ __forceinline__ void mma_tf32(float& c0, float& c1, float& c2, float& c3,
                                         float a0, float a1, float a2, float a3,
                                         float b0, float b1) {
    asm volatile(
        "mma.sync.aligned.m16n8k8.row.col.f32.tf32.tf32.f32 "
        "{%0,%1,%2,%3}, {%4,%5,%6,%7}, {%8,%9}, {%0,%1,%2,%3};"
        : "+f"(c0), "+f"(c1), "+f"(c2), "+f"(c3)
        : "r"(__float_as_uint(a0)), "r"(__float_as_uint(a1)),
          "r"(__float_as_uint(a2)), "r"(__float_as_uint(a3)),
          "r"(__float_as_uint(b0)), "r"(__float_as_uint(b1)));
}

// ---------------------------------------------------------------------------
// im2col: x[B,C,224,224] -> patch[MP, 768] with col = c*256 + i*16 + j
// ---------------------------------------------------------------------------
__global__ void k_im2col(const float* __restrict__ x, float* __restrict__ patch) {
    int idx = blockIdx.x * 256 + threadIdx.x;
    if (idx >= MP_ * E_) return;
    int row = idx / E_;
    int k   = idx - row * E_;
    int b   = row / NP_;
    int p   = row - b * NP_;
    int hp  = p / 14, wp = p - hp * 14;
    int c   = k >> 8;
    int i   = (k >> 4) & 15;
    int j   = k & 15;
    patch[idx] = x[((size_t)(b * C_ + c) * IMG_ + hp * P_ + i) * IMG_ + wp * P_ + j];
}

// ---------------------------------------------------------------------------
// assemble: X[b,0,:] = cls + pos[0]; X[b,t,:] = PE[b,t-1,:] + pos[t]
// ---------------------------------------------------------------------------
__global__ void k_assemble(const float* __restrict__ pe, const float* __restrict__ cls,
                           const float* __restrict__ pos, float* __restrict__ X) {
    int idx = blockIdx.x * 256 + threadIdx.x;
    if (idx >= M_ * E_) return;
    int row = idx / E_;
    int e   = idx - row * E_;
    int b   = row / N_;
    int t   = row - b * N_;
    float v;
    if (t == 0) v = cls[e] + pos[e];
    else        v = pe[(size_t)(b * NP_ + (t - 1)) * E_ + e] + pos[(size_t)t * E_ + e];
    X[idx] = v;
}

// ---------------------------------------------------------------------------
// TF32 tensor-core GEMM (TN): C[M,N] = A[M,K] * B[N,K]^T + bias, opt. GELU.
// BM=BN=128, BK=16. 8 warps in 2x4; warp tile 64x32 of m16n8k8 MMAs.
// K must be a multiple of 16 (true here: 768, 3072).
// ---------------------------------------------------------------------------
__global__ __launch_bounds__(256) void k_mma_gemm(
    const float* __restrict__ A, const float* __restrict__ Bw,
    const float* __restrict__ bias, float* __restrict__ C,
    int M, int N, int K, int act) {
    __shared__ float As[128][17];
    __shared__ float Bs[128][17];

    const int tid  = threadIdx.x;
    const int row0 = blockIdx.y * 128;
    const int col0 = blockIdx.x * 128;

    const int warp = tid >> 5;
    const int lane = tid & 31;
    const int lq   = lane >> 2;   // 0..7
    const int lr   = lane & 3;    // 0..3
    const int wm0  = (warp >> 2) * 64;   // 0 or 64
    const int wn0  = (warp & 3) * 32;    // 0,32,64,96

    // global load mapping: 4 threads per row (float4), 64 rows/pass, 2 passes
    const int grow = tid >> 2;          // 0..63
    const int gk   = (tid & 3) * 4;     // 0,4,8,12

    float acc[4][4][4];
#pragma unroll
    for (int mt = 0; mt < 4; mt++)
#pragma unroll
        for (int nt = 0; nt < 4; nt++)
#pragma unroll
            for (int i = 0; i < 4; i++) acc[mt][nt][i] = 0.f;

    float4 ra[2], rb[2];

    auto load_tile = [&](int k0) {
#pragma unroll
        for (int p = 0; p < 2; p++) {
            int ar = row0 + grow + p * 64;
            int br = col0 + grow + p * 64;
            ra[p] = (ar < M) ? *(const float4*)(A  + (size_t)ar * K + k0 + gk)
                             : make_float4(0.f, 0.f, 0.f, 0.f);
            rb[p] = (br < N) ? *(const float4*)(Bw + (size_t)br * K + k0 + gk)
                             : make_float4(0.f, 0.f, 0.f, 0.f);
        }
    };
    auto store_tile = [&]() {
#pragma unroll
        for (int p = 0; p < 2; p++) {
            int r = grow + p * 64;
            As[r][gk + 0] = to_tf32(ra[p].x); As[r][gk + 1] = to_tf32(ra[p].y);
            As[r][gk + 2] = to_tf32(ra[p].z); As[r][gk + 3] = to_tf32(ra[p].w);
            Bs[r][gk + 0] = to_tf32(rb[p].x); Bs[r][gk + 1] = to_tf32(rb[p].y);
            Bs[r][gk + 2] = to_tf32(rb[p].z); Bs[r][gk + 3] = to_tf32(rb[p].w);
        }
    };
    auto compute_tile = [&]() {
#pragma unroll
        for (int kk = 0; kk < 16; kk += 8) {
            float bf[4][2];
#pragma unroll
            for (int nt = 0; nt < 4; nt++) {
                bf[nt][0] = Bs[wn0 + nt * 8 + lq][kk + lr];
                bf[nt][1] = Bs[wn0 + nt * 8 + lq][kk + lr + 4];
            }
#pragma unroll
            for (int mt = 0; mt < 4; mt++) {
                float a0 = As[wm0 + mt * 16 + lq][kk + lr];
                float a1 = As[wm0 + mt * 16 + lq + 8][kk + lr];
                float a2 = As[wm0 + mt * 16 + lq][kk + lr + 4];
                float a3 = As[wm0 + mt * 16 + lq + 8][kk + lr + 4];
#pragma unroll
                for (int nt = 0; nt < 4; nt++)
                    mma_tf32(acc[mt][nt][0], acc[mt][nt][1],
                             acc[mt][nt][2], acc[mt][nt][3],
                             a0, a1, a2, a3, bf[nt][0], bf[nt][1]);
            }
        }
    };

    load_tile(0);
    store_tile();
    __syncthreads();

    for (int k0 = 16; k0 < K; k0 += 16) {
        load_tile(k0);
        compute_tile();
        __syncthreads();
        store_tile();
        __syncthreads();
    }
    compute_tile();

    // epilogue
#pragma unroll
    for (int mt = 0; mt < 4; mt++) {
#pragma unroll
        for (int half = 0; half < 2; half++) {
            int r = row0 + wm0 + mt * 16 + lq + half * 8;
            if (r >= M) continue;
            float* cr = C + (size_t)r * N;
#pragma unroll
            for (int nt = 0; nt < 4; nt++) {
                int c = col0 + wn0 + nt * 8 + 2 * lr;
                float v0 = acc[mt][nt][half * 2 + 0];
                float v1 = acc[mt][nt][half * 2 + 1];
                if (c < N) {
                    if (bias) v0 += bias[c];
                    if (act) v0 = gelu_f(v0);
                    cr[c] = v0;
                }
                if (c + 1 < N) {
                    if (bias) v1 += bias[c + 1];
                    if (act) v1 = gelu_f(v1);
                    cr[c + 1] = v1;
                }
            }
        }
    }
}

// ---------------------------------------------------------------------------
// Fused attention: one block per (b, head). K,V staged in smem (stride 97).
// softmax over keys, then * SCALE (faithful to reference).
// ---------------------------------------------------------------------------
__global__ void k_attn(const float* __restrict__ QKV, float* __restrict__ OUT) {
    const int b = blockIdx.x >> 3;
    const int h = blockIdx.x & 7;
    extern __shared__ float sm[];
    float* Ks = sm;                       // [197*97]
    float* Vs = Ks + N_ * 97;             // [197*97]
    float* Ps = Vs + N_ * 97;             // [8*197]
    float* Qs = Ps + 8 * N_;              // [8*96]

    const float* base = QKV + (size_t)b * N_ * (3 * E_);
    const int tid = threadIdx.x;

    for (int idx = tid; idx < N_ * HD_; idx += 256) {
        int t = idx / HD_, d = idx - t * HD_;
        const float* rp = base + (size_t)t * (3 * E_) + h * HD_;
        Ks[t * 97 + d] = rp[E_ + d];
        Vs[t * 97 + d] = rp[2 * E_ + d];
    }
    __syncthreads();

    const int warp = tid >> 5, lane = tid & 31;
    int jcl[7];
#pragma unroll
    for (int jj = 0; jj < 7; jj++) {
        int j = jj * 32 + lane;
        jcl[jj] = (j < N_ ? j : N_ - 1) * 97;
    }

    for (int q = warp; q < N_; q += 8) {
        const float* qp = base + (size_t)(q) * (3 * E_) + h * HD_;
        Qs[warp * HD_ + lane]      = qp[lane];
        Qs[warp * HD_ + lane + 32] = qp[lane + 32];
        Qs[warp * HD_ + lane + 64] = qp[lane + 64];
        __syncwarp();

        float s[7];
#pragma unroll
        for (int jj = 0; jj < 7; jj++) s[jj] = 0.f;
#pragma unroll 4
        for (int d = 0; d < HD_; d++) {
            float qd = Qs[warp * HD_ + d];
#pragma unroll
            for (int jj = 0; jj < 7; jj++) s[jj] += qd * Ks[jcl[jj] + d];
        }

        float mx = -1e30f;
#pragma unroll
        for (int jj = 0; jj < 7; jj++)
            if (jj * 32 + lane < N_) mx = fmaxf(mx, s[jj]);
#pragma unroll
        for (int o = 16; o > 0; o >>= 1)
            mx = fmaxf(mx, __shfl_xor_sync(0xffffffffu, mx, o));

        float sum = 0.f;
#pragma unroll
        for (int jj = 0; jj < 7; jj++) {
            float e = (jj * 32 + lane < N_) ? __expf(s[jj] - mx) : 0.f;
            s[jj] = e;
            sum += e;
        }
#pragma unroll
        for (int o = 16; o > 0; o >>= 1)
            sum += __shfl_xor_sync(0xffffffffu, sum, o);

        const float inv = SCALE_ / sum;   // softmax then *SCALE
#pragma unroll
        for (int jj = 0; jj < 7; jj++) {
            int j = jj * 32 + lane;
            if (j < N_) Ps[warp * N_ + j] = s[jj] * inv;
        }
        __syncwarp();

        float a0 = 0.f, a1 = 0.f, a2 = 0.f;
        for (int j = 0; j < N_; j++) {
            float p = Ps[warp * N_ + j];
            const float* vr = Vs + j * 97;
            a0 += p * vr[lane];
            a1 += p * vr[lane + 32];
            a2 += p * vr[lane + 64];
        }
        float* op = OUT + ((size_t)(b * N_ + q)) * E_ + h * HD_;
        op[lane]      = a0;
        op[lane + 32] = a1;
        op[lane + 64] = a2;
        __syncwarp();
    }
}

// ---------------------------------------------------------------------------
// add + LayerNorm per row of E_=768 (R may be nullptr => plain LN).
// ---------------------------------------------------------------------------
__global__ void k_add_ln(const float* __restrict__ Xin, const float* __restrict__ R,
                         float* __restrict__ Xout, const float* __restrict__ g,
                         const float* __restrict__ bt) {
    const int row = blockIdx.x;
    const int tid = threadIdx.x;
    const float* xr = Xin + (size_t)row * E_;
    const float* rr = R ? R + (size_t)row * E_ : nullptr;

    float v[3];
    float sum = 0.f, sq = 0.f;
#pragma unroll
    for (int c = 0; c < 3; c++) {
        int e = tid + c * 256;
        float t = xr[e] + (rr ? rr[e] : 0.f);
        v[c] = t;
        sum += t;
        sq += t * t;
    }
#pragma unroll
    for (int o = 16; o > 0; o >>= 1) {
        sum += __shfl_xor_sync(0xffffffffu, sum, o);
        sq  += __shfl_xor_sync(0xffffffffu, sq, o);
    }
    __shared__ float rs[8], rq[8];
    const int warp = tid >> 5, lane = tid & 31;
    if (lane == 0) { rs[warp] = sum; rq[warp] = sq; }
    __syncthreads();
    sum = 0.f; sq = 0.f;
#pragma unroll
    for (int w = 0; w < 8; w++) { sum += rs[w]; sq += rq[w]; }

    const float m   = sum * (1.f / E_);
    const float var = sq * (1.f / E_) - m * m;
    const float inv = rsqrtf(var + EPS_);
    float* orow = Xout + (size_t)row * E_;
#pragma unroll
    for (int c = 0; c < 3; c++) {
        int e = tid + c * 256;
        orow[e] = (v[c] - m) * inv * g[e] + bt[e];
    }
}

// ---------------------------------------------------------------------------
// mean pool over tokens
// ---------------------------------------------------------------------------
__global__ void k_pool(const float* __restrict__ X, float* __restrict__ P) {
    const int b = blockIdx.x / 3;
    const int e = (blockIdx.x % 3) * 256 + threadIdx.x;
    const float* xp = X + (size_t)b * N_ * E_ + e;
    float s = 0.f;
    for (int t = 0; t < N_; t++) s += xp[(size_t)t * E_];
    P[b * E_ + e] = s * (1.f / N_);
}

// ---------------------------------------------------------------------------
// host
// ---------------------------------------------------------------------------
extern "C" void kernel_launch(void* const* d_in, const int* in_sizes, int n_in,
                              void* d_out, int out_size) {
    const float* x      = (const float*)d_in[0];
    const float* conv_w = (const float*)d_in[1];
    const float* conv_b = (const float*)d_in[2];
    const float* cls    = (const float*)d_in[3];
    const float* pos    = (const float*)d_in[4];
    const float* qkv_w  = (const float*)d_in[5];
    const float* qkv_b  = (const float*)d_in[6];
    const float* proj_w = (const float*)d_in[7];
    const float* proj_b = (const float*)d_in[8];
    const float* ln1_g  = (const float*)d_in[9];
    const float* ln1_b  = (const float*)d_in[10];
    const float* mlp_w1 = (const float*)d_in[11];
    const float* mlp_b1 = (const float*)d_in[12];
    const float* mlp_w2 = (const float*)d_in[13];
    const float* mlp_b2 = (const float*)d_in[14];
    const float* ln2_g  = (const float*)d_in[15];
    const float* ln2_b  = (const float*)d_in[16];
    const float* hln_g  = (const float*)d_in[17];
    const float* hln_b  = (const float*)d_in[18];
    const float* head_w = (const float*)d_in[19];
    const float* head_b = (const float*)d_in[20];
    float* out = (float*)d_out;

    float* pool = nullptr;
    cudaGetSymbolAddress((void**)&pool, g_pool);
    float* X     = pool + oX;
    float* PATCH = pool + oPATCH;
    float* PE    = pool + oPE;
    float* QKV   = pool + oQKV;
    float* ATT   = pool + oATT;
    float* HID   = pool + oHID;
    float* T2    = pool + oT2;
    float* POOL  = pool + oPOOL;
    float* POOLN = pool + oPOOLN;

    const int attn_smem = (int)((2 * N_ * 97 + 8 * N_ + 8 * HD_) * sizeof(float));
    cudaFuncSetAttribute(k_attn, cudaFuncAttributeMaxDynamicSharedMemorySize, attn_smem);

    // patch embed
    k_im2col<<<(MP_ * E_ + 255) / 256, 256>>>(x, PATCH);
    {
        dim3 g((E_ + 127) / 128, (MP_ + 127) / 128);
        k_mma_gemm<<<g, 256>>>(PATCH, conv_w, conv_b, PE, MP_, E_, E_, 0);
    }
    k_assemble<<<(M_ * E_ + 255) / 256, 256>>>(PE, cls, pos, X);

    for (int l = 0; l < L_; l++) {
        const float* qw  = qkv_w  + (size_t)l * 3 * E_ * E_;
        const float* qb  = qkv_b  + (size_t)l * 3 * E_;
        const float* pw  = proj_w + (size_t)l * E_ * E_;
        const float* pb  = proj_b + (size_t)l * E_;
        const float* g1g = ln1_g  + (size_t)l * E_;
        const float* g1b = ln1_b  + (size_t)l * E_;
        const float* w1  = mlp_w1 + (size_t)l * FF_ * E_;
        const float* b1  = mlp_b1 + (size_t)l * FF_;
        const float* w2  = mlp_w2 + (size_t)l * E_ * FF_;
        const float* b2  = mlp_b2 + (size_t)l * E_;
        const float* g2g = ln2_g  + (size_t)l * E_;
        const float* g2b = ln2_b  + (size_t)l * E_;

        {
            dim3 g((3 * E_ + 127) / 128, (M_ + 127) / 128);
            k_mma_gemm<<<g, 256>>>(X, qw, qb, QKV, M_, 3 * E_, E_, 0);
        }
        k_attn<<<B_ * H_, 256, attn_smem>>>(QKV, ATT);
        {
            dim3 g((E_ + 127) / 128, (M_ + 127) / 128);
            k_mma_gemm<<<g, 256>>>(ATT, pw, pb, T2, M_, E_, E_, 0);
        }
        k_add_ln<<<M_, 256>>>(X, T2, X, g1g, g1b);
        {
            dim3 g((FF_ + 127) / 128, (M_ + 127) / 128);
            k_mma_gemm<<<g, 256>>>(X, w1, b1, HID, M_, FF_, E_, 1);
        }
        {
            dim3 g((E_ + 127) / 128, (M_ + 127) / 128);
            k_mma_gemm<<<g, 256>>>(HID, w2, b2, T2, M_, E_, FF_, 0);
        }
        k_add_ln<<<M_, 256>>>(X, T2, X, g2g, g2b);
    }

    // classifier head
    k_pool<<<B_ * 3, 256>>>(X, POOL);
    k_add_ln<<<B_, 256>>>(POOL, nullptr, POOLN, hln_g, hln_b);
    {
        dim3 g((NC_ + 127) / 128, (B_ + 127) / 128);
        k_mma_gemm<<<g, 256>>>(POOLN, head_w, head_b, out, B_, NC_, E_, 0);
    }
}

// round 4
// speedup vs baseline: 2.4271x; 1.1725x over previous
#include <cuda_runtime.h>
#include <cstdint>
#include <math.h>

// ---------------------------------------------------------------------------
// ViT forward. B=32, L=6, E=768, H=8, HD=96, N=197 tokens.
// Round 4: TF32 mma.sync GEMM, 128x256 block / 64x64 warp tiles, cp.async
// double buffering, conflict-free pad-20 smem layout. (R3 + missing header)
// ---------------------------------------------------------------------------

namespace {
constexpr int B_   = 32;
constexpr int C_   = 3;
constexpr int IMG_ = 224;
constexpr int P_   = 16;
constexpr int E_   = 768;
constexpr int H_   = 8;
constexpr int L_   = 6;
constexpr int NC_  = 1000;
constexpr int HD_  = 96;          // E/H
constexpr int NP_  = 196;         // (IMG/P)^2
constexpr int N_   = 197;         // NP + cls
constexpr int M_   = B_ * N_;     // 6304 token rows
constexpr int MP_  = B_ * NP_;    // 6272 patch rows
constexpr int FF_  = 4 * E_;      // 3072
constexpr float SCALE_ = 0.1020620726159657f;  // HD^-0.5
constexpr float EPS_   = 1e-5f;

// scratch pool layout (floats)
constexpr size_t oX     = 0;
constexpr size_t oPATCH = oX     + (size_t)M_ * E_;
constexpr size_t oPE    = oPATCH + (size_t)MP_ * E_;
constexpr size_t oQKV   = oPE    + (size_t)MP_ * E_;
constexpr size_t oATT   = oQKV   + (size_t)M_ * 3 * E_;
constexpr size_t oHID   = oATT   + (size_t)M_ * E_;
constexpr size_t oT2    = oHID   + (size_t)M_ * FF_;
constexpr size_t oPOOL  = oT2    + (size_t)M_ * E_;
constexpr size_t oPOOLN = oPOOL  + (size_t)B_ * E_;
constexpr size_t TOT    = oPOOLN + (size_t)B_ * E_;

// GEMM smem geometry (floats)
constexpr int PAD_  = 20;                 // 16 k-cols + 4 pad -> conflict-free
constexpr int ASZ_  = 128 * PAD_;         // one A stage
constexpr int BSZ_  = 256 * PAD_;         // one B stage
constexpr int GSMEM = (2 * ASZ_ + 2 * BSZ_) * 4;   // bytes = 61440
}  // namespace

__device__ float g_pool[TOT];

// ---------------------------------------------------------------------------
// helpers
// ---------------------------------------------------------------------------
__device__ __forceinline__ float gelu_f(float x) {
    return 0.5f * x * (1.f + erff(x * 0.7071067811865475f));
}

__device__ __forceinline__ float to_tf32(float x) {
    asm("cvt.rna.tf32.f32 %0, %0;" : "+f"(x));
    return x;
}

__device__ __forceinline__ void mma_tf32(float* c,
                                         float a0, float a1, float a2, float a3,
                                         float b0, float b1) {
    asm volatile(
        "mma.sync.aligned.m16n8k8.row.col.f32.tf32.tf32.f32 "
        "{%0,%1,%2,%3}, {%4,%5,%6,%7}, {%8,%9}, {%0,%1,%2,%3};"
        : "+f"(c[0]), "+f"(c[1]), "+f"(c[2]), "+f"(c[3])
        : "r"(__float_as_uint(a0)), "r"(__float_as_uint(a1)),
          "r"(__float_as_uint(a2)), "r"(__float_as_uint(a3)),
          "r"(__float_as_uint(b0)), "r"(__float_as_uint(b1)));
}

__device__ __forceinline__ void cp16(float* dst, const float* src) {
    unsigned int d = (unsigned int)__cvta_generic_to_shared(dst);
    asm volatile("cp.async.ca.shared.global [%0], [%1], 16;" :: "r"(d), "l"(src));
}
__device__ __forceinline__ void cp_commit() {
    asm volatile("cp.async.commit_group;");
}
__device__ __forceinline__ void cp_wait0() {
    asm volatile("cp.async.wait_group 0;");
}

// ---------------------------------------------------------------------------
// im2col: x[B,C,224,224] -> patch[MP, 768] with col = c*256 + i*16 + j
// ---------------------------------------------------------------------------
__global__ void k_im2col(const float* __restrict__ x, float* __restrict__ patch) {
    int idx = blockIdx.x * 256 + threadIdx.x;
    if (idx >= MP_ * E_) return;
    int row = idx / E_;
    int k   = idx - row * E_;
    int b   = row / NP_;
    int p   = row - b * NP_;
    int hp  = p / 14, wp = p - hp * 14;
    int c   = k >> 8;
    int i   = (k >> 4) & 15;
    int j   = k & 15;
    patch[idx] = x[((size_t)(b * C_ + c) * IMG_ + hp * P_ + i) * IMG_ + wp * P_ + j];
}

// ---------------------------------------------------------------------------
// assemble: X[b,0,:] = cls + pos[0]; X[b,t,:] = PE[b,t-1,:] + pos[t]
// ---------------------------------------------------------------------------
__global__ void k_assemble(const float* __restrict__ pe, const float* __restrict__ cls,
                           const float* __restrict__ pos, float* __restrict__ X) {
    int idx = blockIdx.x * 256 + threadIdx.x;
    if (idx >= M_ * E_) return;
    int row = idx / E_;
    int e   = idx - row * E_;
    int b   = row / N_;
    int t   = row - b * N_;
    float v;
    if (t == 0) v = cls[e] + pos[e];
    else        v = pe[(size_t)(b * NP_ + (t - 1)) * E_ + e] + pos[(size_t)t * E_ + e];
    X[idx] = v;
}

// ---------------------------------------------------------------------------
// TF32 tensor-core GEMM (TN): C[M,N] = A[M,K] * B[N,K]^T + bias, opt. GELU.
// Block tile 128x256, BK=16, 8 warps (2x4), warp tile 64x64.
// cp.async double buffer, one __syncthreads per BK.
// K must be a multiple of 16.
// ---------------------------------------------------------------------------
__global__ __launch_bounds__(256) void k_mma_gemm(
    const float* __restrict__ A, const float* __restrict__ Bw,
    const float* __restrict__ bias, float* __restrict__ C,
    int M, int N, int K, int act) {
    extern __shared__ float sm[];
    float* As = sm;                 // [2][128][PAD_]
    float* Bs = sm + 2 * ASZ_;      // [2][256][PAD_]

    const int tid  = threadIdx.x;
    const int row0 = blockIdx.y * 128;
    const int col0 = blockIdx.x * 256;

    const int warp = tid >> 5;
    const int lane = tid & 31;
    const int lq   = lane >> 2;          // 0..7
    const int lr   = lane & 3;           // 0..3
    const int wm0  = (warp >> 2) * 64;   // 0 or 64
    const int wn0  = (warp & 3) * 64;    // 0,64,128,192

    // global loader mapping: 4 threads per row, 16B each
    const int lrow = tid >> 2;           // 0..63
    const int lgk  = (tid & 3) * 4;      // 0,4,8,12

    const float* aptr[2];
    const float* bptr[4];
#pragma unroll
    for (int p = 0; p < 2; p++) {
        int r = row0 + lrow + p * 64;
        aptr[p] = A + (size_t)(r < M ? r : M - 1) * K + lgk;
    }
#pragma unroll
    for (int p = 0; p < 4; p++) {
        int r = col0 + lrow + p * 64;
        bptr[p] = Bw + (size_t)(r < N ? r : N - 1) * K + lgk;
    }

    float acc[4][8][4];
#pragma unroll
    for (int mt = 0; mt < 4; mt++)
#pragma unroll
        for (int nt = 0; nt < 8; nt++)
#pragma unroll
            for (int i = 0; i < 4; i++) acc[mt][nt][i] = 0.f;

    auto issue = [&](int t, int s) {
        const int k0 = t * 16;
        float* as = As + s * ASZ_;
        float* bs = Bs + s * BSZ_;
#pragma unroll
        for (int p = 0; p < 2; p++)
            cp16(as + (lrow + p * 64) * PAD_ + lgk, aptr[p] + k0);
#pragma unroll
        for (int p = 0; p < 4; p++)
            cp16(bs + (lrow + p * 64) * PAD_ + lgk, bptr[p] + k0);
        cp_commit();
    };

    auto compute = [&](int s) {
        const float* as = As + s * ASZ_;
        const float* bs = Bs + s * BSZ_;
#pragma unroll
        for (int kk = 0; kk < 16; kk += 8) {
            float bf[8][2];
#pragma unroll
            for (int nt = 0; nt < 8; nt++) {
                const float* bp = bs + (wn0 + nt * 8 + lq) * PAD_ + kk + lr;
                bf[nt][0] = to_tf32(bp[0]);
                bf[nt][1] = to_tf32(bp[4]);
            }
#pragma unroll
            for (int mt = 0; mt < 4; mt++) {
                const float* ap = as + (wm0 + mt * 16 + lq) * PAD_ + kk + lr;
                float a0 = to_tf32(ap[0]);
                float a1 = to_tf32(ap[8 * PAD_]);
                float a2 = to_tf32(ap[4]);
                float a3 = to_tf32(ap[8 * PAD_ + 4]);
#pragma unroll
                for (int nt = 0; nt < 8; nt++)
                    mma_tf32(acc[mt][nt], a0, a1, a2, a3, bf[nt][0], bf[nt][1]);
            }
        }
    };

    const int T = K >> 4;
    issue(0, 0);
    for (int t = 0; t < T; t++) {
        cp_wait0();
        __syncthreads();
        if (t + 1 < T) issue(t + 1, (t + 1) & 1);
        compute(t & 1);
    }

    // epilogue
#pragma unroll
    for (int mt = 0; mt < 4; mt++) {
#pragma unroll
        for (int half = 0; half < 2; half++) {
            int r = row0 + wm0 + mt * 16 + lq + half * 8;
            if (r >= M) continue;
            float* cr = C + (size_t)r * N;
#pragma unroll
            for (int nt = 0; nt < 8; nt++) {
                int c = col0 + wn0 + nt * 8 + 2 * lr;
                float v0 = acc[mt][nt][half * 2 + 0];
                float v1 = acc[mt][nt][half * 2 + 1];
                if (c < N) {
                    if (bias) v0 += bias[c];
                    if (act) v0 = gelu_f(v0);
                    cr[c] = v0;
                }
                if (c + 1 < N) {
                    if (bias) v1 += bias[c + 1];
                    if (act) v1 = gelu_f(v1);
                    cr[c + 1] = v1;
                }
            }
        }
    }
}

// ---------------------------------------------------------------------------
// Fused attention: one block per (b, head). K,V staged in smem (stride 97).
// softmax over keys, then * SCALE (faithful to reference).
// ---------------------------------------------------------------------------
__global__ void k_attn(const float* __restrict__ QKV, float* __restrict__ OUT) {
    const int b = blockIdx.x >> 3;
    const int h = blockIdx.x & 7;
    extern __shared__ float smA[];
    float* Ks = smA;                      // [197*97]
    float* Vs = Ks + N_ * 97;             // [197*97]
    float* Ps = Vs + N_ * 97;             // [8*197]
    float* Qs = Ps + 8 * N_;              // [8*96]

    const float* base = QKV + (size_t)b * N_ * (3 * E_);
    const int tid = threadIdx.x;

    for (int idx = tid; idx < N_ * HD_; idx += 256) {
        int t = idx / HD_, d = idx - t * HD_;
        const float* rp = base + (size_t)t * (3 * E_) + h * HD_;
        Ks[t * 97 + d] = rp[E_ + d];
        Vs[t * 97 + d] = rp[2 * E_ + d];
    }
    __syncthreads();

    const int warp = tid >> 5, lane = tid & 31;
    int jcl[7];
#pragma unroll
    for (int jj = 0; jj < 7; jj++) {
        int j = jj * 32 + lane;
        jcl[jj] = (j < N_ ? j : N_ - 1) * 97;
    }

    for (int q = warp; q < N_; q += 8) {
        const float* qp = base + (size_t)(q) * (3 * E_) + h * HD_;
        Qs[warp * HD_ + lane]      = qp[lane];
        Qs[warp * HD_ + lane + 32] = qp[lane + 32];
        Qs[warp * HD_ + lane + 64] = qp[lane + 64];
        __syncwarp();

        float s[7];
#pragma unroll
        for (int jj = 0; jj < 7; jj++) s[jj] = 0.f;
#pragma unroll 4
        for (int d = 0; d < HD_; d++) {
            float qd = Qs[warp * HD_ + d];
#pragma unroll
            for (int jj = 0; jj < 7; jj++) s[jj] += qd * Ks[jcl[jj] + d];
        }

        float mx = -1e30f;
#pragma unroll
        for (int jj = 0; jj < 7; jj++)
            if (jj * 32 + lane < N_) mx = fmaxf(mx, s[jj]);
#pragma unroll
        for (int o = 16; o > 0; o >>= 1)
            mx = fmaxf(mx, __shfl_xor_sync(0xffffffffu, mx, o));

        float sum = 0.f;
#pragma unroll
        for (int jj = 0; jj < 7; jj++) {
            float e = (jj * 32 + lane < N_) ? __expf(s[jj] - mx) : 0.f;
            s[jj] = e;
            sum += e;
        }
#pragma unroll
        for (int o = 16; o > 0; o >>= 1)
            sum += __shfl_xor_sync(0xffffffffu, sum, o);

        const float inv = SCALE_ / sum;   // softmax then *SCALE
#pragma unroll
        for (int jj = 0; jj < 7; jj++) {
            int j = jj * 32 + lane;
            if (j < N_) Ps[warp * N_ + j] = s[jj] * inv;
        }
        __syncwarp();

        float a0 = 0.f, a1 = 0.f, a2 = 0.f;
        for (int j = 0; j < N_; j++) {
            float p = Ps[warp * N_ + j];
            const float* vr = Vs + j * 97;
            a0 += p * vr[lane];
            a1 += p * vr[lane + 32];
            a2 += p * vr[lane + 64];
        }
        float* op = OUT + ((size_t)(b * N_ + q)) * E_ + h * HD_;
        op[lane]      = a0;
        op[lane + 32] = a1;
        op[lane + 64] = a2;
        __syncwarp();
    }
}

// ---------------------------------------------------------------------------
// add + LayerNorm per row of E_=768 (R may be nullptr => plain LN).
// ---------------------------------------------------------------------------
__global__ void k_add_ln(const float* __restrict__ Xin, const float* __restrict__ R,
                         float* __restrict__ Xout, const float* __restrict__ g,
                         const float* __restrict__ bt) {
    const int row = blockIdx.x;
    const int tid = threadIdx.x;
    const float* xr = Xin + (size_t)row * E_;
    const float* rr = R ? R + (size_t)row * E_ : nullptr;

    float v[3];
    float sum = 0.f, sq = 0.f;
#pragma unroll
    for (int c = 0; c < 3; c++) {
        int e = tid + c * 256;
        float t = xr[e] + (rr ? rr[e] : 0.f);
        v[c] = t;
        sum += t;
        sq += t * t;
    }
#pragma unroll
    for (int o = 16; o > 0; o >>= 1) {
        sum += __shfl_xor_sync(0xffffffffu, sum, o);
        sq  += __shfl_xor_sync(0xffffffffu, sq, o);
    }
    __shared__ float rs[8], rq[8];
    const int warp = tid >> 5, lane = tid & 31;
    if (lane == 0) { rs[warp] = sum; rq[warp] = sq; }
    __syncthreads();
    sum = 0.f; sq = 0.f;
#pragma unroll
    for (int w = 0; w < 8; w++) { sum += rs[w]; sq += rq[w]; }

    const float m   = sum * (1.f / E_);
    const float var = sq * (1.f / E_) - m * m;
    const float inv = rsqrtf(var + EPS_);
    float* orow = Xout + (size_t)row * E_;
#pragma unroll
    for (int c = 0; c < 3; c++) {
        int e = tid + c * 256;
        orow[e] = (v[c] - m) * inv * g[e] + bt[e];
    }
}

// ---------------------------------------------------------------------------
// mean pool over tokens
// ---------------------------------------------------------------------------
__global__ void k_pool(const float* __restrict__ X, float* __restrict__ P) {
    const int b = blockIdx.x / 3;
    const int e = (blockIdx.x % 3) * 256 + threadIdx.x;
    const float* xp = X + (size_t)b * N_ * E_ + e;
    float s = 0.f;
    for (int t = 0; t < N_; t++) s += xp[(size_t)t * E_];
    P[b * E_ + e] = s * (1.f / N_);
}

// ---------------------------------------------------------------------------
// host
// ---------------------------------------------------------------------------
extern "C" void kernel_launch(void* const* d_in, const int* in_sizes, int n_in,
                              void* d_out, int out_size) {
    const float* x      = (const float*)d_in[0];
    const float* conv_w = (const float*)d_in[1];
    const float* conv_b = (const float*)d_in[2];
    const float* cls    = (const float*)d_in[3];
    const float* pos    = (const float*)d_in[4];
    const float* qkv_w  = (const float*)d_in[5];
    const float* qkv_b  = (const float*)d_in[6];
    const float* proj_w = (const float*)d_in[7];
    const float* proj_b = (const float*)d_in[8];
    const float* ln1_g  = (const float*)d_in[9];
    const float* ln1_b  = (const float*)d_in[10];
    const float* mlp_w1 = (const float*)d_in[11];
    const float* mlp_b1 = (const float*)d_in[12];
    const float* mlp_w2 = (const float*)d_in[13];
    const float* mlp_b2 = (const float*)d_in[14];
    const float* ln2_g  = (const float*)d_in[15];
    const float* ln2_b  = (const float*)d_in[16];
    const float* hln_g  = (const float*)d_in[17];
    const float* hln_b  = (const float*)d_in[18];
    const float* head_w = (const float*)d_in[19];
    const float* head_b = (const float*)d_in[20];
    float* out = (float*)d_out;

    float* pool = nullptr;
    cudaGetSymbolAddress((void**)&pool, g_pool);
    float* X     = pool + oX;
    float* PATCH = pool + oPATCH;
    float* PE    = pool + oPE;
    float* QKV   = pool + oQKV;
    float* ATT   = pool + oATT;
    float* HID   = pool + oHID;
    float* T2    = pool + oT2;
    float* POOL  = pool + oPOOL;
    float* POOLN = pool + oPOOLN;

    const int attn_smem = (int)((2 * N_ * 97 + 8 * N_ + 8 * HD_) * sizeof(float));
    cudaFuncSetAttribute(k_attn, cudaFuncAttributeMaxDynamicSharedMemorySize, attn_smem);
    cudaFuncSetAttribute(k_mma_gemm, cudaFuncAttributeMaxDynamicSharedMemorySize, GSMEM);

    auto gemm = [&](const float* A, const float* Bw, const float* bias, float* Cst,
                    int M, int N, int K, int act) {
        dim3 g((N + 255) / 256, (M + 127) / 128);
        k_mma_gemm<<<g, 256, GSMEM>>>(A, Bw, bias, Cst, M, N, K, act);
    };

    // patch embed
    k_im2col<<<(MP_ * E_ + 255) / 256, 256>>>(x, PATCH);
    gemm(PATCH, conv_w, conv_b, PE, MP_, E_, E_, 0);
    k_assemble<<<(M_ * E_ + 255) / 256, 256>>>(PE, cls, pos, X);

    for (int l = 0; l < L_; l++) {
        const float* qw  = qkv_w  + (size_t)l * 3 * E_ * E_;
        const float* qb  = qkv_b  + (size_t)l * 3 * E_;
        const float* pw  = proj_w + (size_t)l * E_ * E_;
        const float* pb  = proj_b + (size_t)l * E_;
        const float* g1g = ln1_g  + (size_t)l * E_;
        const float* g1b = ln1_b  + (size_t)l * E_;
        const float* w1  = mlp_w1 + (size_t)l * FF_ * E_;
        const float* b1  = mlp_b1 + (size_t)l * FF_;
        const float* w2  = mlp_w2 + (size_t)l * E_ * FF_;
        const float* b2  = mlp_b2 + (size_t)l * E_;
        const float* g2g = ln2_g  + (size_t)l * E_;
        const float* g2b = ln2_b  + (size_t)l * E_;

        gemm(X, qw, qb, QKV, M_, 3 * E_, E_, 0);
        k_attn<<<B_ * H_, 256, attn_smem>>>(QKV, ATT);
        gemm(ATT, pw, pb, T2, M_, E_, E_, 0);
        k_add_ln<<<M_, 256>>>(X, T2, X, g1g, g1b);
        gemm(X, w1, b1, HID, M_, FF_, E_, 1);
        gemm(HID, w2, b2, T2, M_, E_, FF_, 0);
        k_add_ln<<<M_, 256>>>(X, T2, X, g2g, g2b);
    }

    // classifier head
    k_pool<<<B_ * 3, 256>>>(X, POOL);
    k_add_ln<<<B_, 256>>>(POOL, nullptr, POOLN, hln_g, hln_b);
    gemm(POOLN, head_w, head_b, out, B_, NC_, E_, 0);
}

// round 5
// speedup vs baseline: 2.4747x; 1.0196x over previous
#include <cuda_runtime.h>
#include <cstdint>
#include <math.h>

// ---------------------------------------------------------------------------
// ViT forward. B=32, L=6, E=768, H=8, HD=96, N=197 tokens.
// Round 5: TF32 mma.sync GEMM, 128x256 block / 64x64 warp tiles,
// 4-stage cp.async.cg pipeline (wait_group 2), pad-20 smem.
// ---------------------------------------------------------------------------

namespace {
constexpr int B_   = 32;
constexpr int C_   = 3;
constexpr int IMG_ = 224;
constexpr int P_   = 16;
constexpr int E_   = 768;
constexpr int H_   = 8;
constexpr int L_   = 6;
constexpr int NC_  = 1000;
constexpr int HD_  = 96;          // E/H
constexpr int NP_  = 196;         // (IMG/P)^2
constexpr int N_   = 197;         // NP + cls
constexpr int M_   = B_ * N_;     // 6304 token rows
constexpr int MP_  = B_ * NP_;    // 6272 patch rows
constexpr int FF_  = 4 * E_;      // 3072
constexpr float SCALE_ = 0.1020620726159657f;  // HD^-0.5
constexpr float EPS_   = 1e-5f;

// scratch pool layout (floats)
constexpr size_t oX     = 0;
constexpr size_t oPATCH = oX     + (size_t)M_ * E_;
constexpr size_t oPE    = oPATCH + (size_t)MP_ * E_;
constexpr size_t oQKV   = oPE    + (size_t)MP_ * E_;
constexpr size_t oATT   = oQKV   + (size_t)M_ * 3 * E_;
constexpr size_t oHID   = oATT   + (size_t)M_ * E_;
constexpr size_t oT2    = oHID   + (size_t)M_ * FF_;
constexpr size_t oPOOL  = oT2    + (size_t)M_ * E_;
constexpr size_t oPOOLN = oPOOL  + (size_t)B_ * E_;
constexpr size_t TOT    = oPOOLN + (size_t)B_ * E_;

// GEMM smem geometry (floats)
constexpr int PAD_   = 20;                // 16 k-cols + 4 pad -> conflict-free
constexpr int ASZ_   = 128 * PAD_;        // one A stage
constexpr int BSZ_   = 256 * PAD_;        // one B stage
constexpr int STAGES = 4;
constexpr int GSMEM  = STAGES * (ASZ_ + BSZ_) * 4;   // 122880 bytes
}  // namespace

__device__ float g_pool[TOT];

// ---------------------------------------------------------------------------
// helpers
// ---------------------------------------------------------------------------
__device__ __forceinline__ float gelu_f(float x) {
    return 0.5f * x * (1.f + erff(x * 0.7071067811865475f));
}

__device__ __forceinline__ float to_tf32(float x) {
    asm("cvt.rna.tf32.f32 %0, %0;" : "+f"(x));
    return x;
}

__device__ __forceinline__ void mma_tf32(float* c,
                                         float a0, float a1, float a2, float a3,
                                         float b0, float b1) {
    asm volatile(
        "mma.sync.aligned.m16n8k8.row.col.f32.tf32.tf32.f32 "
        "{%0,%1,%2,%3}, {%4,%5,%6,%7}, {%8,%9}, {%0,%1,%2,%3};"
        : "+f"(c[0]), "+f"(c[1]), "+f"(c[2]), "+f"(c[3])
        : "r"(__float_as_uint(a0)), "r"(__float_as_uint(a1)),
          "r"(__float_as_uint(a2)), "r"(__float_as_uint(a3)),
          "r"(__float_as_uint(b0)), "r"(__float_as_uint(b1)));
}

__device__ __forceinline__ void cp16(float* dst, const float* src) {
    unsigned int d = (unsigned int)__cvta_generic_to_shared(dst);
    asm volatile("cp.async.cg.shared.global [%0], [%1], 16;" :: "r"(d), "l"(src));
}
__device__ __forceinline__ void cp_commit() {
    asm volatile("cp.async.commit_group;");
}
template <int Nn>
__device__ __forceinline__ void cp_wait() {
    asm volatile("cp.async.wait_group %0;" :: "n"(Nn));
}

// ---------------------------------------------------------------------------
// im2col: x[B,C,224,224] -> patch[MP, 768] with col = c*256 + i*16 + j
// ---------------------------------------------------------------------------
__global__ void k_im2col(const float* __restrict__ x, float* __restrict__ patch) {
    int idx = blockIdx.x * 256 + threadIdx.x;
    if (idx >= MP_ * E_) return;
    int row = idx / E_;
    int k   = idx - row * E_;
    int b   = row / NP_;
    int p   = row - b * NP_;
    int hp  = p / 14, wp = p - hp * 14;
    int c   = k >> 8;
    int i   = (k >> 4) & 15;
    int j   = k & 15;
    patch[idx] = x[((size_t)(b * C_ + c) * IMG_ + hp * P_ + i) * IMG_ + wp * P_ + j];
}

// ---------------------------------------------------------------------------
// assemble: X[b,0,:] = cls + pos[0]; X[b,t,:] = PE[b,t-1,:] + pos[t]
// ---------------------------------------------------------------------------
__global__ void k_assemble(const float* __restrict__ pe, const float* __restrict__ cls,
                           const float* __restrict__ pos, float* __restrict__ X) {
    int idx = blockIdx.x * 256 + threadIdx.x;
    if (idx >= M_ * E_) return;
    int row = idx / E_;
    int e   = idx - row * E_;
    int b   = row / N_;
    int t   = row - b * N_;
    float v;
    if (t == 0) v = cls[e] + pos[e];
    else        v = pe[(size_t)(b * NP_ + (t - 1)) * E_ + e] + pos[(size_t)t * E_ + e];
    X[idx] = v;
}

// ---------------------------------------------------------------------------
// TF32 tensor-core GEMM (TN): C[M,N] = A[M,K] * B[N,K]^T + bias, opt. GELU.
// Block tile 128x256, BK=16, 8 warps (2x4), warp tile 64x64.
// 4-stage cp.async ring, one __syncthreads per BK tile.
// K must be a multiple of 16 and >= 48 (all our K are 768/3072).
// ---------------------------------------------------------------------------
__global__ __launch_bounds__(256) void k_mma_gemm(
    const float* __restrict__ A, const float* __restrict__ Bw,
    const float* __restrict__ bias, float* __restrict__ C,
    int M, int N, int K, int act) {
    extern __shared__ float sm[];
    float* As = sm;                        // [STAGES][128][PAD_]
    float* Bs = sm + STAGES * ASZ_;        // [STAGES][256][PAD_]

    const int tid  = threadIdx.x;
    const int row0 = blockIdx.y * 128;
    const int col0 = blockIdx.x * 256;

    const int warp = tid >> 5;
    const int lane = tid & 31;
    const int lq   = lane >> 2;          // 0..7
    const int lr   = lane & 3;           // 0..3
    const int wm0  = (warp >> 2) * 64;   // 0 or 64
    const int wn0  = (warp & 3) * 64;    // 0,64,128,192

    // global loader mapping: 4 threads per row, 16B each
    const int lrow = tid >> 2;           // 0..63
    const int lgk  = (tid & 3) * 4;      // 0,4,8,12

    const float* aptr[2];
    const float* bptr[4];
#pragma unroll
    for (int p = 0; p < 2; p++) {
        int r = row0 + lrow + p * 64;
        aptr[p] = A + (size_t)(r < M ? r : M - 1) * K + lgk;
    }
#pragma unroll
    for (int p = 0; p < 4; p++) {
        int r = col0 + lrow + p * 64;
        bptr[p] = Bw + (size_t)(r < N ? r : N - 1) * K + lgk;
    }

    float acc[4][8][4];
#pragma unroll
    for (int mt = 0; mt < 4; mt++)
#pragma unroll
        for (int nt = 0; nt < 8; nt++)
#pragma unroll
            for (int i = 0; i < 4; i++) acc[mt][nt][i] = 0.f;

    auto issue = [&](int t, int s) {
        const int k0 = t * 16;
        float* as = As + s * ASZ_;
        float* bs = Bs + s * BSZ_;
#pragma unroll
        for (int p = 0; p < 2; p++)
            cp16(as + (lrow + p * 64) * PAD_ + lgk, aptr[p] + k0);
#pragma unroll
        for (int p = 0; p < 4; p++)
            cp16(bs + (lrow + p * 64) * PAD_ + lgk, bptr[p] + k0);
        cp_commit();
    };

    auto compute = [&](int s) {
        const float* as = As + s * ASZ_;
        const float* bs = Bs + s * BSZ_;
#pragma unroll
        for (int kk = 0; kk < 16; kk += 8) {
            float bf[8][2];
#pragma unroll
            for (int nt = 0; nt < 8; nt++) {
                const float* bp = bs + (wn0 + nt * 8 + lq) * PAD_ + kk + lr;
                bf[nt][0] = to_tf32(bp[0]);
                bf[nt][1] = to_tf32(bp[4]);
            }
#pragma unroll
            for (int mt = 0; mt < 4; mt++) {
                const float* ap = as + (wm0 + mt * 16 + lq) * PAD_ + kk + lr;
                float a0 = to_tf32(ap[0]);
                float a1 = to_tf32(ap[8 * PAD_]);
                float a2 = to_tf32(ap[4]);
                float a3 = to_tf32(ap[8 * PAD_ + 4]);
#pragma unroll
                for (int nt = 0; nt < 8; nt++)
                    mma_tf32(acc[mt][nt], a0, a1, a2, a3, bf[nt][0], bf[nt][1]);
            }
        }
    };

    const int T = K >> 4;
    issue(0, 0);
    issue(1, 1);
    issue(2, 2);
    for (int t = 0; t < T; t++) {
        cp_wait<2>();            // stage t's loads complete
        __syncthreads();         // also: all warps done reading recycled stage
        if (t + 3 < T) issue(t + 3, (t + 3) & (STAGES - 1));
        compute(t & (STAGES - 1));
    }

    // epilogue
#pragma unroll
    for (int mt = 0; mt < 4; mt++) {
#pragma unroll
        for (int half = 0; half < 2; half++) {
            int r = row0 + wm0 + mt * 16 + lq + half * 8;
            if (r >= M) continue;
            float* cr = C + (size_t)r * N;
#pragma unroll
            for (int nt = 0; nt < 8; nt++) {
                int c = col0 + wn0 + nt * 8 + 2 * lr;
                float v0 = acc[mt][nt][half * 2 + 0];
                float v1 = acc[mt][nt][half * 2 + 1];
                if (c < N) {
                    if (bias) v0 += bias[c];
                    if (act) v0 = gelu_f(v0);
                    cr[c] = v0;
                }
                if (c + 1 < N) {
                    if (bias) v1 += bias[c + 1];
                    if (act) v1 = gelu_f(v1);
                    cr[c + 1] = v1;
                }
            }
        }
    }
}

// ---------------------------------------------------------------------------
// Fused attention: one block per (b, head). K,V staged in smem (stride 97).
// softmax over keys, then * SCALE (faithful to reference).
// ---------------------------------------------------------------------------
__global__ void k_attn(const float* __restrict__ QKV, float* __restrict__ OUT) {
    const int b = blockIdx.x >> 3;
    const int h = blockIdx.x & 7;
    extern __shared__ float smA[];
    float* Ks = smA;                      // [197*97]
    float* Vs = Ks + N_ * 97;             // [197*97]
    float* Ps = Vs + N_ * 97;             // [8*197]
    float* Qs = Ps + 8 * N_;              // [8*96]

    const float* base = QKV + (size_t)b * N_ * (3 * E_);
    const int tid = threadIdx.x;

    for (int idx = tid; idx < N_ * HD_; idx += 256) {
        int t = idx / HD_, d = idx - t * HD_;
        const float* rp = base + (size_t)t * (3 * E_) + h * HD_;
        Ks[t * 97 + d] = rp[E_ + d];
        Vs[t * 97 + d] = rp[2 * E_ + d];
    }
    __syncthreads();

    const int warp = tid >> 5, lane = tid & 31;
    int jcl[7];
#pragma unroll
    for (int jj = 0; jj < 7; jj++) {
        int j = jj * 32 + lane;
        jcl[jj] = (j < N_ ? j : N_ - 1) * 97;
    }

    for (int q = warp; q < N_; q += 8) {
        const float* qp = base + (size_t)(q) * (3 * E_) + h * HD_;
        Qs[warp * HD_ + lane]      = qp[lane];
        Qs[warp * HD_ + lane + 32] = qp[lane + 32];
        Qs[warp * HD_ + lane + 64] = qp[lane + 64];
        __syncwarp();

        float s[7];
#pragma unroll
        for (int jj = 0; jj < 7; jj++) s[jj] = 0.f;
#pragma unroll 4
        for (int d = 0; d < HD_; d++) {
            float qd = Qs[warp * HD_ + d];
#pragma unroll
            for (int jj = 0; jj < 7; jj++) s[jj] += qd * Ks[jcl[jj] + d];
        }

        float mx = -1e30f;
#pragma unroll
        for (int jj = 0; jj < 7; jj++)
            if (jj * 32 + lane < N_) mx = fmaxf(mx, s[jj]);
#pragma unroll
        for (int o = 16; o > 0; o >>= 1)
            mx = fmaxf(mx, __shfl_xor_sync(0xffffffffu, mx, o));

        float sum = 0.f;
#pragma unroll
        for (int jj = 0; jj < 7; jj++) {
            float e = (jj * 32 + lane < N_) ? __expf(s[jj] - mx) : 0.f;
            s[jj] = e;
            sum += e;
        }
#pragma unroll
        for (int o = 16; o > 0; o >>= 1)
            sum += __shfl_xor_sync(0xffffffffu, sum, o);

        const float inv = SCALE_ / sum;   // softmax then *SCALE
#pragma unroll
        for (int jj = 0; jj < 7; jj++) {
            int j = jj * 32 + lane;
            if (j < N_) Ps[warp * N_ + j] = s[jj] * inv;
        }
        __syncwarp();

        float a0 = 0.f, a1 = 0.f, a2 = 0.f;
        for (int j = 0; j < N_; j++) {
            float p = Ps[warp * N_ + j];
            const float* vr = Vs + j * 97;
            a0 += p * vr[lane];
            a1 += p * vr[lane + 32];
            a2 += p * vr[lane + 64];
        }
        float* op = OUT + ((size_t)(b * N_ + q)) * E_ + h * HD_;
        op[lane]      = a0;
        op[lane + 32] = a1;
        op[lane + 64] = a2;
        __syncwarp();
    }
}

// ---------------------------------------------------------------------------
// add + LayerNorm per row of E_=768 (R may be nullptr => plain LN).
// ---------------------------------------------------------------------------
__global__ void k_add_ln(const float* __restrict__ Xin, const float* __restrict__ R,
                         float* __restrict__ Xout, const float* __restrict__ g,
                         const float* __restrict__ bt) {
    const int row = blockIdx.x;
    const int tid = threadIdx.x;
    const float* xr = Xin + (size_t)row * E_;
    const float* rr = R ? R + (size_t)row * E_ : nullptr;

    float v[3];
    float sum = 0.f, sq = 0.f;
#pragma unroll
    for (int c = 0; c < 3; c++) {
        int e = tid + c * 256;
        float t = xr[e] + (rr ? rr[e] : 0.f);
        v[c] = t;
        sum += t;
        sq += t * t;
    }
#pragma unroll
    for (int o = 16; o > 0; o >>= 1) {
        sum += __shfl_xor_sync(0xffffffffu, sum, o);
        sq  += __shfl_xor_sync(0xffffffffu, sq, o);
    }
    __shared__ float rs[8], rq[8];
    const int warp = tid >> 5, lane = tid & 31;
    if (lane == 0) { rs[warp] = sum; rq[warp] = sq; }
    __syncthreads();
    sum = 0.f; sq = 0.f;
#pragma unroll
    for (int w = 0; w < 8; w++) { sum += rs[w]; sq += rq[w]; }

    const float m   = sum * (1.f / E_);
    const float var = sq * (1.f / E_) - m * m;
    const float inv = rsqrtf(var + EPS_);
    float* orow = Xout + (size_t)row * E_;
#pragma unroll
    for (int c = 0; c < 3; c++) {
        int e = tid + c * 256;
        orow[e] = (v[c] - m) * inv * g[e] + bt[e];
    }
}

// ---------------------------------------------------------------------------
// mean pool over tokens
// ---------------------------------------------------------------------------
__global__ void k_pool(const float* __restrict__ X, float* __restrict__ P) {
    const int b = blockIdx.x / 3;
    const int e = (blockIdx.x % 3) * 256 + threadIdx.x;
    const float* xp = X + (size_t)b * N_ * E_ + e;
    float s = 0.f;
    for (int t = 0; t < N_; t++) s += xp[(size_t)t * E_];
    P[b * E_ + e] = s * (1.f / N_);
}

// ---------------------------------------------------------------------------
// host
// ---------------------------------------------------------------------------
extern "C" void kernel_launch(void* const* d_in, const int* in_sizes, int n_in,
                              void* d_out, int out_size) {
    const float* x      = (const float*)d_in[0];
    const float* conv_w = (const float*)d_in[1];
    const float* conv_b = (const float*)d_in[2];
    const float* cls    = (const float*)d_in[3];
    const float* pos    = (const float*)d_in[4];
    const float* qkv_w  = (const float*)d_in[5];
    const float* qkv_b  = (const float*)d_in[6];
    const float* proj_w = (const float*)d_in[7];
    const float* proj_b = (const float*)d_in[8];
    const float* ln1_g  = (const float*)d_in[9];
    const float* ln1_b  = (const float*)d_in[10];
    const float* mlp_w1 = (const float*)d_in[11];
    const float* mlp_b1 = (const float*)d_in[12];
    const float* mlp_w2 = (const float*)d_in[13];
    const float* mlp_b2 = (const float*)d_in[14];
    const float* ln2_g  = (const float*)d_in[15];
    const float* ln2_b  = (const float*)d_in[16];
    const float* hln_g  = (const float*)d_in[17];
    const float* hln_b  = (const float*)d_in[18];
    const float* head_w = (const float*)d_in[19];
    const float* head_b = (const float*)d_in[20];
    float* out = (float*)d_out;

    float* pool = nullptr;
    cudaGetSymbolAddress((void**)&pool, g_pool);
    float* X     = pool + oX;
    float* PATCH = pool + oPATCH;
    float* PE    = pool + oPE;
    float* QKV   = pool + oQKV;
    float* ATT   = pool + oATT;
    float* HID   = pool + oHID;
    float* T2    = pool + oT2;
    float* POOL  = pool + oPOOL;
    float* POOLN = pool + oPOOLN;

    const int attn_smem = (int)((2 * N_ * 97 + 8 * N_ + 8 * HD_) * sizeof(float));
    cudaFuncSetAttribute(k_attn, cudaFuncAttributeMaxDynamicSharedMemorySize, attn_smem);
    cudaFuncSetAttribute(k_mma_gemm, cudaFuncAttributeMaxDynamicSharedMemorySize, GSMEM);

    auto gemm = [&](const float* A, const float* Bw, const float* bias, float* Cst,
                    int M, int N, int K, int act) {
        dim3 g((N + 255) / 256, (M + 127) / 128);
        k_mma_gemm<<<g, 256, GSMEM>>>(A, Bw, bias, Cst, M, N, K, act);
    };

    // patch embed
    k_im2col<<<(MP_ * E_ + 255) / 256, 256>>>(x, PATCH);
    gemm(PATCH, conv_w, conv_b, PE, MP_, E_, E_, 0);
    k_assemble<<<(M_ * E_ + 255) / 256, 256>>>(PE, cls, pos, X);

    for (int l = 0; l < L_; l++) {
        const float* qw  = qkv_w  + (size_t)l * 3 * E_ * E_;
        const float* qb  = qkv_b  + (size_t)l * 3 * E_;
        const float* pw  = proj_w + (size_t)l * E_ * E_;
        const float* pb  = proj_b + (size_t)l * E_;
        const float* g1g = ln1_g  + (size_t)l * E_;
        const float* g1b = ln1_b  + (size_t)l * E_;
        const float* w1  = mlp_w1 + (size_t)l * FF_ * E_;
        const float* b1  = mlp_b1 + (size_t)l * FF_;
        const float* w2  = mlp_w2 + (size_t)l * E_ * FF_;
        const float* b2  = mlp_b2 + (size_t)l * E_;
        const float* g2g = ln2_g  + (size_t)l * E_;
        const float* g2b = ln2_b  + (size_t)l * E_;

        gemm(X, qw, qb, QKV, M_, 3 * E_, E_, 0);
        k_attn<<<B_ * H_, 256, attn_smem>>>(QKV, ATT);
        gemm(ATT, pw, pb, T2, M_, E_, E_, 0);
        k_add_ln<<<M_, 256>>>(X, T2, X, g1g, g1b);
        gemm(X, w1, b1, HID, M_, FF_, E_, 1);
        gemm(HID, w2, b2, T2, M_, E_, FF_, 0);
        k_add_ln<<<M_, 256>>>(X, T2, X, g2g, g2b);
    }

    // classifier head
    k_pool<<<B_ * 3, 256>>>(X, POOL);
    k_add_ln<<<B_, 256>>>(POOL, nullptr, POOLN, hln_g, hln_b);
    gemm(POOLN, head_w, head_b, out, B_, NC_, E_, 0);
}

// round 7
// speedup vs baseline: 2.5965x; 1.0492x over previous
#include <cuda_runtime.h>
#include <cstdint>
#include <math.h>

// ---------------------------------------------------------------------------
// ViT forward. B=32, L=6, E=768, H=8, HD=96, N=197 tokens.
// Round 7: TF32 mma.sync GEMM with k-permuted operand layout (LDS.128
// fragment loads, zero mainloop CVTs), RNA pre-rounded operands, 4-stage
// cp.async ring. Permutation p=(c&~15)|((c&3)<<2)|((c>>2)&3) is an involution.
// ---------------------------------------------------------------------------

namespace {
constexpr int B_   = 32;
constexpr int C_   = 3;
constexpr int IMG_ = 224;
constexpr int P_   = 16;
constexpr int E_   = 768;
constexpr int H_   = 8;
constexpr int L_   = 6;
constexpr int NC_  = 1000;
constexpr int HD_  = 96;
constexpr int NP_  = 196;
constexpr int N_   = 197;
constexpr int M_   = B_ * N_;     // 6304
constexpr int MP_  = B_ * NP_;    // 6272
constexpr int FF_  = 4 * E_;      // 3072
constexpr float SCALE_ = 0.1020620726159657f;
constexpr float EPS_   = 1e-5f;

// GEMM smem geometry (floats): BK=16, stride 16 (no pad), 4 stages
constexpr int STAGES = 4;
constexpr int AST_ = 128 * 16;                      // 2048 floats / stage
constexpr int BST_ = 256 * 16;                      // 4096 floats / stage
constexpr int GSMEM = STAGES * (AST_ + BST_) * 4;   // 98304 bytes

// scratch pool layout (floats)
constexpr size_t oX     = 0;
constexpr size_t oPATCH = oX     + (size_t)M_ * E_;
constexpr size_t oPE    = oPATCH + (size_t)MP_ * E_;
constexpr size_t oQKV   = oPE    + (size_t)MP_ * E_;
constexpr size_t oATT   = oQKV   + (size_t)M_ * 3 * E_;
constexpr size_t oHID   = oATT   + (size_t)M_ * E_;
constexpr size_t oT2    = oHID   + (size_t)M_ * FF_;
constexpr size_t oPOOL  = oT2    + (size_t)M_ * E_;
constexpr size_t oPOOLN = oPOOL  + (size_t)B_ * E_;
constexpr size_t oWC    = oPOOLN + (size_t)B_ * E_;
constexpr size_t oWQ    = oWC    + (size_t)E_ * E_;
constexpr size_t oWP    = oWQ    + (size_t)L_ * 3 * E_ * E_;
constexpr size_t oW1    = oWP    + (size_t)L_ * E_ * E_;
constexpr size_t oW2    = oW1    + (size_t)L_ * FF_ * E_;
constexpr size_t oWH    = oW2    + (size_t)L_ * E_ * FF_;
constexpr size_t TOT    = oWH    + (size_t)NC_ * E_;
}  // namespace

__device__ float g_pool[TOT];

// ---------------------------------------------------------------------------
// helpers
// ---------------------------------------------------------------------------
__device__ __forceinline__ int dperm(int c) {       // involution, within 16-block
    return (c & ~15) | ((c & 3) << 2) | ((c >> 2) & 3);
}
__device__ __forceinline__ float gelu_f(float x) {
    return 0.5f * x * (1.f + erff(x * 0.7071067811865475f));
}
__device__ __forceinline__ float rna_tf32(float x) {
    asm("cvt.rna.tf32.f32 %0, %0;" : "+f"(x));
    return x;
}
__device__ __forceinline__ void mma_tf32(float* c,
                                         float a0, float a1, float a2, float a3,
                                         float b0, float b1) {
    asm volatile(
        "mma.sync.aligned.m16n8k8.row.col.f32.tf32.tf32.f32 "
        "{%0,%1,%2,%3}, {%4,%5,%6,%7}, {%8,%9}, {%0,%1,%2,%3};"
        : "+f"(c[0]), "+f"(c[1]), "+f"(c[2]), "+f"(c[3])
        : "r"(__float_as_uint(a0)), "r"(__float_as_uint(a1)),
          "r"(__float_as_uint(a2)), "r"(__float_as_uint(a3)),
          "r"(__float_as_uint(b0)), "r"(__float_as_uint(b1)));
}
__device__ __forceinline__ void cp16(float* dst, const float* src) {
    unsigned d = (unsigned)__cvta_generic_to_shared(dst);
    asm volatile("cp.async.cg.shared.global [%0], [%1], 16;" :: "r"(d), "l"(src));
}
__device__ __forceinline__ void cp_commit() { asm volatile("cp.async.commit_group;"); }
template <int Nn>
__device__ __forceinline__ void cp_wait() {
    asm volatile("cp.async.wait_group %0;" :: "n"(Nn));
}

// ---------------------------------------------------------------------------
// weight copy: RNA round + k-permute within 16-blocks of the K dim
// ---------------------------------------------------------------------------
__global__ void k_round_perm(const float* __restrict__ in, float* __restrict__ o,
                             int n, int K) {
    int i = blockIdx.x * 256 + threadIdx.x;
    if (i >= n) return;
    int row = i / K;
    int k   = i - row * K;
    o[(size_t)row * K + dperm(k)] = rna_tf32(in[i]);
}

// ---------------------------------------------------------------------------
// im2col: permuted+rounded output
// ---------------------------------------------------------------------------
__global__ void k_im2col(const float* __restrict__ x, float* __restrict__ patch) {
    int idx = blockIdx.x * 256 + threadIdx.x;
    if (idx >= MP_ * E_) return;
    int row = idx / E_;
    int k   = idx - row * E_;
    int b   = row / NP_;
    int p   = row - b * NP_;
    int hp  = p / 14, wp = p - hp * 14;
    int c   = k >> 8;
    int i   = (k >> 4) & 15;
    int j   = k & 15;
    patch[(size_t)row * E_ + dperm(k)] = rna_tf32(
        x[((size_t)(b * C_ + c) * IMG_ + hp * P_ + i) * IMG_ + wp * P_ + j]);
}

// ---------------------------------------------------------------------------
// assemble: reads PE natural, writes X permuted+rounded
// ---------------------------------------------------------------------------
__global__ void k_assemble(const float* __restrict__ pe, const float* __restrict__ cls,
                           const float* __restrict__ pos, float* __restrict__ X) {
    int idx = blockIdx.x * 256 + threadIdx.x;
    if (idx >= M_ * E_) return;
    int row = idx / E_;
    int e   = idx - row * E_;
    int b   = row / N_;
    int t   = row - b * N_;
    float v;
    if (t == 0) v = cls[e] + pos[e];
    else        v = pe[(size_t)(b * NP_ + (t - 1)) * E_ + e] + pos[(size_t)t * E_ + e];
    X[(size_t)row * E_ + dperm(e)] = rna_tf32(v);
}

// ---------------------------------------------------------------------------
// TF32 mma GEMM (TN): C[M,N] = A[M,K]*B[N,K]^T + bias. Operands k-permuted
// in gmem. 128x256 block, 64x64 warp tile, BK=16, LDS.128 fragments.
// act: GELU+round. pout: write columns permuted (output feeds a GEMM as A).
// ---------------------------------------------------------------------------
__global__ __launch_bounds__(256) void k_mma_gemm(
    const float* __restrict__ A, const float* __restrict__ Bw,
    const float* __restrict__ bias, float* __restrict__ C,
    int M, int N, int K, int act, int pout) {
    extern __shared__ __align__(16) float sm[];
    float* As = sm;                         // [STAGES][128][16]
    float* Bs = sm + STAGES * AST_;         // [STAGES][256][16]

    const int tid  = threadIdx.x;
    const int row0 = blockIdx.y * 128;
    const int col0 = blockIdx.x * 256;

    const int warp = tid >> 5;
    const int lane = tid & 31;
    const int lq   = lane >> 2;          // 0..7
    const int lr   = lane & 3;           // 0..3
    const int wm0  = (warp >> 2) * 64;   // 0 or 64
    const int wn0  = (warp & 3) * 64;    // 0,64,128,192

    float acc[4][8][4];
#pragma unroll
    for (int mt = 0; mt < 4; mt++)
#pragma unroll
        for (int nt = 0; nt < 8; nt++)
#pragma unroll
            for (int i = 0; i < 4; i++) acc[mt][nt][i] = 0.f;

    // loader mapping: 4 threads per row, 16B each (row stride 16 floats)
    const float* aptr[2];
    const float* bptr[4];
#pragma unroll
    for (int p = 0; p < 2; p++) {
        int cidx = tid + p * 256;        // 0..511
        int r = row0 + (cidx >> 2);
        aptr[p] = A + (size_t)(r < M ? r : M - 1) * K + (cidx & 3) * 4;
    }
#pragma unroll
    for (int p = 0; p < 4; p++) {
        int cidx = tid + p * 256;        // 0..1023
        int r = col0 + (cidx >> 2);
        bptr[p] = Bw + (size_t)(r < N ? r : N - 1) * K + (cidx & 3) * 4;
    }

    auto issue = [&](int t) {
        const int s  = t & (STAGES - 1);
        const int k0 = t * 16;
        float* as = As + s * AST_;
        float* bs = Bs + s * BST_;
#pragma unroll
        for (int p = 0; p < 2; p++) {
            int cidx = tid + p * 256;
            cp16(as + (cidx >> 2) * 16 + (cidx & 3) * 4, aptr[p] + k0);
        }
#pragma unroll
        for (int p = 0; p < 4; p++) {
            int cidx = tid + p * 256;
            cp16(bs + (cidx >> 2) * 16 + (cidx & 3) * 4, bptr[p] + k0);
        }
        cp_commit();
    };

    auto compute = [&](int s) {
        const float* as = As + s * AST_;
        const float* bs = Bs + s * BST_;
        float4 bv[8];
#pragma unroll
        for (int nt = 0; nt < 8; nt++)
            bv[nt] = *(const float4*)(bs + (wn0 + nt * 8 + lq) * 16 + lr * 4);
#pragma unroll
        for (int mt = 0; mt < 4; mt++) {
            float4 al = *(const float4*)(as + (wm0 + mt * 16 + lq) * 16 + lr * 4);
            float4 ah = *(const float4*)(as + (wm0 + mt * 16 + lq + 8) * 16 + lr * 4);
#pragma unroll
            for (int nt = 0; nt < 8; nt++)
                mma_tf32(acc[mt][nt], al.x, ah.x, al.y, ah.y, bv[nt].x, bv[nt].y);
#pragma unroll
            for (int nt = 0; nt < 8; nt++)
                mma_tf32(acc[mt][nt], al.z, ah.z, al.w, ah.w, bv[nt].z, bv[nt].w);
        }
    };

    const int T = K >> 4;
    issue(0); issue(1); issue(2);
    for (int t = 0; t < T; t++) {
        cp_wait<2>();
        __syncthreads();
        if (t + 3 < T) issue(t + 3);
        compute(t & (STAGES - 1));
    }

    // epilogue
#pragma unroll
    for (int mt = 0; mt < 4; mt++) {
#pragma unroll
        for (int half = 0; half < 2; half++) {
            int r = row0 + wm0 + mt * 16 + lq + half * 8;
            if (r >= M) continue;
            float* cr = C + (size_t)r * N;
#pragma unroll
            for (int nt = 0; nt < 8; nt++) {
                int c = col0 + wn0 + nt * 8 + 2 * lr;
#pragma unroll
                for (int u = 0; u < 2; u++) {
                    int cc = c + u;
                    if (cc >= N) continue;
                    float v = acc[mt][nt][half * 2 + u];
                    if (bias) v += bias[cc];
                    if (act)  v = rna_tf32(gelu_f(v));
                    cr[pout ? dperm(cc) : cc] = v;
                }
            }
        }
    }
}

// ---------------------------------------------------------------------------
// Fused attention: reads QKV natural, writes ATT permuted+rounded.
// ---------------------------------------------------------------------------
__global__ void k_attn(const float* __restrict__ QKV, float* __restrict__ OUT) {
    const int b = blockIdx.x >> 3;
    const int h = blockIdx.x & 7;
    extern __shared__ float smA[];
    float* Ks = smA;                      // [197*97]
    float* Vs = Ks + N_ * 97;             // [197*97]
    float* Ps = Vs + N_ * 97;             // [8*197]
    float* Qs = Ps + 8 * N_;              // [8*96]

    const float* base = QKV + (size_t)b * N_ * (3 * E_);
    const int tid = threadIdx.x;

    for (int idx = tid; idx < N_ * HD_; idx += 256) {
        int t = idx / HD_, d = idx - t * HD_;
        const float* rp = base + (size_t)t * (3 * E_) + h * HD_;
        Ks[t * 97 + d] = rp[E_ + d];
        Vs[t * 97 + d] = rp[2 * E_ + d];
    }
    __syncthreads();

    const int warp = tid >> 5, lane = tid & 31;
    int jcl[7];
#pragma unroll
    for (int jj = 0; jj < 7; jj++) {
        int j = jj * 32 + lane;
        jcl[jj] = (j < N_ ? j : N_ - 1) * 97;
    }

    const int p0 = dperm(lane), p1 = dperm(lane + 32), p2 = dperm(lane + 64);

    for (int q = warp; q < N_; q += 8) {
        const float* qp = base + (size_t)(q) * (3 * E_) + h * HD_;
        Qs[warp * HD_ + lane]      = qp[lane];
        Qs[warp * HD_ + lane + 32] = qp[lane + 32];
        Qs[warp * HD_ + lane + 64] = qp[lane + 64];
        __syncwarp();

        float s[7];
#pragma unroll
        for (int jj = 0; jj < 7; jj++) s[jj] = 0.f;
#pragma unroll 4
        for (int d = 0; d < HD_; d++) {
            float qd = Qs[warp * HD_ + d];
#pragma unroll
            for (int jj = 0; jj < 7; jj++) s[jj] += qd * Ks[jcl[jj] + d];
        }

        float mx = -1e30f;
#pragma unroll
        for (int jj = 0; jj < 7; jj++)
            if (jj * 32 + lane < N_) mx = fmaxf(mx, s[jj]);
#pragma unroll
        for (int o = 16; o > 0; o >>= 1)
            mx = fmaxf(mx, __shfl_xor_sync(0xffffffffu, mx, o));

        float sum = 0.f;
#pragma unroll
        for (int jj = 0; jj < 7; jj++) {
            float e = (jj * 32 + lane < N_) ? __expf(s[jj] - mx) : 0.f;
            s[jj] = e;
            sum += e;
        }
#pragma unroll
        for (int o = 16; o > 0; o >>= 1)
            sum += __shfl_xor_sync(0xffffffffu, sum, o);

        const float inv = SCALE_ / sum;   // softmax then *SCALE
#pragma unroll
        for (int jj = 0; jj < 7; jj++) {
            int j = jj * 32 + lane;
            if (j < N_) Ps[warp * N_ + j] = s[jj] * inv;
        }
        __syncwarp();

        float a0 = 0.f, a1 = 0.f, a2 = 0.f;
        for (int j = 0; j < N_; j++) {
            float p = Ps[warp * N_ + j];
            const float* vr = Vs + j * 97;
            a0 += p * vr[lane];
            a1 += p * vr[lane + 32];
            a2 += p * vr[lane + 64];
        }
        float* op = OUT + ((size_t)(b * N_ + q)) * E_ + h * HD_;
        op[p0] = rna_tf32(a0);
        op[p1] = rna_tf32(a1);
        op[p2] = rna_tf32(a2);
        __syncwarp();
    }
}

// ---------------------------------------------------------------------------
// add + LayerNorm on PERMUTED-layout buffers. Params indexed via dperm
// (involution). Output permuted + rounded.
// ---------------------------------------------------------------------------
__global__ void k_add_ln(const float* __restrict__ Xin, const float* __restrict__ R,
                         float* __restrict__ Xout, const float* __restrict__ g,
                         const float* __restrict__ bt) {
    const int row = blockIdx.x;
    const int tid = threadIdx.x;
    const float* xr = Xin + (size_t)row * E_;
    const float* rr = R ? R + (size_t)row * E_ : nullptr;

    float v[3];
    float sum = 0.f, sq = 0.f;
#pragma unroll
    for (int c = 0; c < 3; c++) {
        int e = tid + c * 256;
        float t = xr[e] + (rr ? rr[e] : 0.f);
        v[c] = t;
        sum += t;
        sq += t * t;
    }
#pragma unroll
    for (int o = 16; o > 0; o >>= 1) {
        sum += __shfl_xor_sync(0xffffffffu, sum, o);
        sq  += __shfl_xor_sync(0xffffffffu, sq, o);
    }
    __shared__ float rs[8], rq[8];
    const int warp = tid >> 5, lane = tid & 31;
    if (lane == 0) { rs[warp] = sum; rq[warp] = sq; }
    __syncthreads();
    sum = 0.f; sq = 0.f;
#pragma unroll
    for (int w = 0; w < 8; w++) { sum += rs[w]; sq += rq[w]; }

    const float m   = sum * (1.f / E_);
    const float var = sq * (1.f / E_) - m * m;
    const float inv = rsqrtf(var + EPS_);
    float* orow = Xout + (size_t)row * E_;
#pragma unroll
    for (int c = 0; c < 3; c++) {
        int e  = tid + c * 256;
        int ne = dperm(e);               // natural column for this storage slot
        orow[e] = rna_tf32((v[c] - m) * inv * g[ne] + bt[ne]);
    }
}

// ---------------------------------------------------------------------------
// mean pool over tokens (storage-order passthrough)
// ---------------------------------------------------------------------------
__global__ void k_pool(const float* __restrict__ X, float* __restrict__ P) {
    const int b = blockIdx.x / 3;
    const int e = (blockIdx.x % 3) * 256 + threadIdx.x;
    const float* xp = X + (size_t)b * N_ * E_ + e;
    float s = 0.f;
    for (int t = 0; t < N_; t++) s += xp[(size_t)t * E_];
    P[b * E_ + e] = s * (1.f / N_);
}

// ---------------------------------------------------------------------------
// host
// ---------------------------------------------------------------------------
extern "C" void kernel_launch(void* const* d_in, const int* in_sizes, int n_in,
                              void* d_out, int out_size) {
    const float* x      = (const float*)d_in[0];
    const float* conv_w = (const float*)d_in[1];
    const float* conv_b = (const float*)d_in[2];
    const float* cls    = (const float*)d_in[3];
    const float* pos    = (const float*)d_in[4];
    const float* qkv_w  = (const float*)d_in[5];
    const float* qkv_b  = (const float*)d_in[6];
    const float* proj_w = (const float*)d_in[7];
    const float* proj_b = (const float*)d_in[8];
    const float* ln1_g  = (const float*)d_in[9];
    const float* ln1_b  = (const float*)d_in[10];
    const float* mlp_w1 = (const float*)d_in[11];
    const float* mlp_b1 = (const float*)d_in[12];
    const float* mlp_w2 = (const float*)d_in[13];
    const float* mlp_b2 = (const float*)d_in[14];
    const float* ln2_g  = (const float*)d_in[15];
    const float* ln2_b  = (const float*)d_in[16];
    const float* hln_g  = (const float*)d_in[17];
    const float* hln_b  = (const float*)d_in[18];
    const float* head_w = (const float*)d_in[19];
    const float* head_b = (const float*)d_in[20];
    float* out = (float*)d_out;

    float* pool = nullptr;
    cudaGetSymbolAddress((void**)&pool, g_pool);
    float* X     = pool + oX;
    float* PATCH = pool + oPATCH;
    float* PE    = pool + oPE;
    float* QKV   = pool + oQKV;
    float* ATT   = pool + oATT;
    float* HID   = pool + oHID;
    float* T2    = pool + oT2;
    float* POOL  = pool + oPOOL;
    float* POOLN = pool + oPOOLN;
    float* WC    = pool + oWC;
    float* WQ    = pool + oWQ;
    float* WP    = pool + oWP;
    float* W1    = pool + oW1;
    float* W2    = pool + oW2;
    float* WH    = pool + oWH;

    const int attn_smem = (int)((2 * N_ * 97 + 8 * N_ + 8 * HD_) * sizeof(float));
    cudaFuncSetAttribute(k_attn, cudaFuncAttributeMaxDynamicSharedMemorySize, attn_smem);
    cudaFuncSetAttribute(k_mma_gemm, cudaFuncAttributeMaxDynamicSharedMemorySize, GSMEM);

    auto prepW = [&](const float* in, float* o, size_t n, int K) {
        k_round_perm<<<(int)((n + 255) / 256), 256>>>(in, o, (int)n, K);
    };
    prepW(conv_w, WC, (size_t)E_ * E_, E_);
    prepW(qkv_w,  WQ, (size_t)L_ * 3 * E_ * E_, E_);
    prepW(proj_w, WP, (size_t)L_ * E_ * E_, E_);
    prepW(mlp_w1, W1, (size_t)L_ * FF_ * E_, E_);
    prepW(mlp_w2, W2, (size_t)L_ * E_ * FF_, FF_);
    prepW(head_w, WH, (size_t)NC_ * E_, E_);

    auto gemm = [&](const float* A, const float* Bw, const float* bias, float* Cst,
                    int M, int N, int K, int act, int pout) {
        dim3 g((N + 255) / 256, (M + 127) / 128);
        k_mma_gemm<<<g, 256, GSMEM>>>(A, Bw, bias, Cst, M, N, K, act, pout);
    };

    // patch embed (PATCH permuted; PE natural; assemble permutes into X)
    k_im2col<<<(MP_ * E_ + 255) / 256, 256>>>(x, PATCH);
    gemm(PATCH, WC, conv_b, PE, MP_, E_, E_, 0, 0);
    k_assemble<<<(M_ * E_ + 255) / 256, 256>>>(PE, cls, pos, X);

    for (int l = 0; l < L_; l++) {
        const float* qw  = WQ + (size_t)l * 3 * E_ * E_;
        const float* qb  = qkv_b  + (size_t)l * 3 * E_;
        const float* pw  = WP + (size_t)l * E_ * E_;
        const float* pb  = proj_b + (size_t)l * E_;
        const float* g1g = ln1_g  + (size_t)l * E_;
        const float* g1b = ln1_b  + (size_t)l * E_;
        const float* w1  = W1 + (size_t)l * FF_ * E_;
        const float* b1  = mlp_b1 + (size_t)l * FF_;
        const float* w2  = W2 + (size_t)l * E_ * FF_;
        const float* b2  = mlp_b2 + (size_t)l * E_;
        const float* g2g = ln2_g  + (size_t)l * E_;
        const float* g2b = ln2_b  + (size_t)l * E_;

        gemm(X, qw, qb, QKV, M_, 3 * E_, E_, 0, 0);       // QKV natural
        k_attn<<<B_ * H_, 256, attn_smem>>>(QKV, ATT);    // ATT permuted
        gemm(ATT, pw, pb, T2, M_, E_, E_, 0, 1);          // T2 permuted
        k_add_ln<<<M_, 256>>>(X, T2, X, g1g, g1b);        // X permuted
        gemm(X, w1, b1, HID, M_, FF_, E_, 1, 1);          // HID permuted (GELU)
        gemm(HID, w2, b2, T2, M_, E_, FF_, 0, 1);         // T2 permuted
        k_add_ln<<<M_, 256>>>(X, T2, X, g2g, g2b);
    }

    // classifier head
    k_pool<<<B_ * 3, 256>>>(X, POOL);                      // POOL permuted
    k_add_ln<<<B_, 256>>>(POOL, nullptr, POOLN, hln_g, hln_b);
    gemm(POOLN, WH, head_b, out, B_, NC_, E_, 0, 0);       // out natural
}

// round 8
// speedup vs baseline: 2.9588x; 1.1396x over previous
#include <cuda_runtime.h>
#include <cstdint>
#include <math.h>

// ---------------------------------------------------------------------------
// ViT forward. B=32, L=6, E=768, H=8, HD=96, N=197 tokens.
// Round 8: TF32 mma.sync GEMM 128x128 block / 64x32 warp tiles, 2 CTAs/SM,
// k-permuted operands (LDS.128 fragments, no mainloop CVTs), 4-stage cp.async.
// ---------------------------------------------------------------------------

namespace {
constexpr int B_   = 32;
constexpr int C_   = 3;
constexpr int IMG_ = 224;
constexpr int P_   = 16;
constexpr int E_   = 768;
constexpr int H_   = 8;
constexpr int L_   = 6;
constexpr int NC_  = 1000;
constexpr int HD_  = 96;
constexpr int NP_  = 196;
constexpr int N_   = 197;
constexpr int M_   = B_ * N_;     // 6304
constexpr int MP_  = B_ * NP_;    // 6272
constexpr int FF_  = 4 * E_;      // 3072
constexpr float SCALE_ = 0.1020620726159657f;
constexpr float EPS_   = 1e-5f;

// GEMM smem geometry (floats): BK=16, row stride 16, 4 stages, BM=BN=128
constexpr int STAGES = 4;
constexpr int AST_ = 128 * 16;                      // 2048 floats / stage
constexpr int BST_ = 128 * 16;                      // 2048 floats / stage
constexpr int GSMEM = STAGES * (AST_ + BST_) * 4;   // 65536 bytes

// scratch pool layout (floats)
constexpr size_t oX     = 0;
constexpr size_t oPATCH = oX     + (size_t)M_ * E_;
constexpr size_t oPE    = oPATCH + (size_t)MP_ * E_;
constexpr size_t oQKV   = oPE    + (size_t)MP_ * E_;
constexpr size_t oATT   = oQKV   + (size_t)M_ * 3 * E_;
constexpr size_t oHID   = oATT   + (size_t)M_ * E_;
constexpr size_t oT2    = oHID   + (size_t)M_ * FF_;
constexpr size_t oPOOL  = oT2    + (size_t)M_ * E_;
constexpr size_t oPOOLN = oPOOL  + (size_t)B_ * E_;
constexpr size_t oWC    = oPOOLN + (size_t)B_ * E_;
constexpr size_t oWQ    = oWC    + (size_t)E_ * E_;
constexpr size_t oWP    = oWQ    + (size_t)L_ * 3 * E_ * E_;
constexpr size_t oW1    = oWP    + (size_t)L_ * E_ * E_;
constexpr size_t oW2    = oW1    + (size_t)L_ * FF_ * E_;
constexpr size_t oWH    = oW2    + (size_t)L_ * E_ * FF_;
constexpr size_t TOT    = oWH    + (size_t)NC_ * E_;
}  // namespace

__device__ float g_pool[TOT];

// ---------------------------------------------------------------------------
// helpers
// ---------------------------------------------------------------------------
__device__ __forceinline__ int dperm(int c) {       // involution, within 16-block
    return (c & ~15) | ((c & 3) << 2) | ((c >> 2) & 3);
}
__device__ __forceinline__ float gelu_f(float x) {
    return 0.5f * x * (1.f + erff(x * 0.7071067811865475f));
}
__device__ __forceinline__ float rna_tf32(float x) {
    asm("cvt.rna.tf32.f32 %0, %0;" : "+f"(x));
    return x;
}
__device__ __forceinline__ void mma_tf32(float* c,
                                         float a0, float a1, float a2, float a3,
                                         float b0, float b1) {
    asm volatile(
        "mma.sync.aligned.m16n8k8.row.col.f32.tf32.tf32.f32 "
        "{%0,%1,%2,%3}, {%4,%5,%6,%7}, {%8,%9}, {%0,%1,%2,%3};"
        : "+f"(c[0]), "+f"(c[1]), "+f"(c[2]), "+f"(c[3])
        : "r"(__float_as_uint(a0)), "r"(__float_as_uint(a1)),
          "r"(__float_as_uint(a2)), "r"(__float_as_uint(a3)),
          "r"(__float_as_uint(b0)), "r"(__float_as_uint(b1)));
}
__device__ __forceinline__ void cp16(float* dst, const float* src) {
    unsigned d = (unsigned)__cvta_generic_to_shared(dst);
    asm volatile("cp.async.cg.shared.global [%0], [%1], 16;" :: "r"(d), "l"(src));
}
__device__ __forceinline__ void cp_commit() { asm volatile("cp.async.commit_group;"); }
template <int Nn>
__device__ __forceinline__ void cp_wait() {
    asm volatile("cp.async.wait_group %0;" :: "n"(Nn));
}

// ---------------------------------------------------------------------------
// weight prep: RNA round + k-permute, float4 stores (gather via involution)
// ---------------------------------------------------------------------------
__global__ void k_round_perm(const float* __restrict__ in, float* __restrict__ o,
                             int n4, int K) {
    int i = blockIdx.x * 256 + threadIdx.x;
    if (i >= n4) return;
    int j   = i * 4;
    int row = j / K;
    int k   = j - row * K;          // multiple of 4
    int hi  = k & ~15;
    int a   = (k >> 2) & 3;
    const float* ir = in + (size_t)row * K + hi + a;
    float4 v;
    v.x = rna_tf32(ir[0]);
    v.y = rna_tf32(ir[4]);
    v.z = rna_tf32(ir[8]);
    v.w = rna_tf32(ir[12]);
    *(float4*)(o + (size_t)row * K + k) = v;
}

// ---------------------------------------------------------------------------
// im2col: permuted+rounded output
// ---------------------------------------------------------------------------
__global__ void k_im2col(const float* __restrict__ x, float* __restrict__ patch) {
    int idx = blockIdx.x * 256 + threadIdx.x;
    if (idx >= MP_ * E_) return;
    int row = idx / E_;
    int k   = idx - row * E_;
    int b   = row / NP_;
    int p   = row - b * NP_;
    int hp  = p / 14, wp = p - hp * 14;
    int c   = k >> 8;
    int i   = (k >> 4) & 15;
    int j   = k & 15;
    patch[(size_t)row * E_ + dperm(k)] = rna_tf32(
        x[((size_t)(b * C_ + c) * IMG_ + hp * P_ + i) * IMG_ + wp * P_ + j]);
}

// ---------------------------------------------------------------------------
// assemble: reads PE natural, writes X permuted+rounded
// ---------------------------------------------------------------------------
__global__ void k_assemble(const float* __restrict__ pe, const float* __restrict__ cls,
                           const float* __restrict__ pos, float* __restrict__ X) {
    int idx = blockIdx.x * 256 + threadIdx.x;
    if (idx >= M_ * E_) return;
    int row = idx / E_;
    int e   = idx - row * E_;
    int b   = row / N_;
    int t   = row - b * N_;
    float v;
    if (t == 0) v = cls[e] + pos[e];
    else        v = pe[(size_t)(b * NP_ + (t - 1)) * E_ + e] + pos[(size_t)t * E_ + e];
    X[(size_t)row * E_ + dperm(e)] = rna_tf32(v);
}

// ---------------------------------------------------------------------------
// TF32 mma GEMM (TN): C[M,N] = A[M,K]*B[N,K]^T + bias. Operands k-permuted.
// 128x128 block, 64x32 warp tile (2x4 warps), BK=16, 4-stage cp.async,
// 2 CTAs/SM. act: GELU+round. pout: permute output columns.
// ---------------------------------------------------------------------------
__global__ __launch_bounds__(256, 2) void k_mma_gemm(
    const float* __restrict__ A, const float* __restrict__ Bw,
    const float* __restrict__ bias, float* __restrict__ C,
    int M, int N, int K, int act, int pout) {
    extern __shared__ __align__(16) float sm[];
    float* As = sm;                         // [STAGES][128][16]
    float* Bs = sm + STAGES * AST_;         // [STAGES][128][16]

    const int tid  = threadIdx.x;
    const int row0 = blockIdx.y * 128;
    const int col0 = blockIdx.x * 128;

    const int warp = tid >> 5;
    const int lane = tid & 31;
    const int lq   = lane >> 2;          // 0..7
    const int lr   = lane & 3;           // 0..3
    const int wm0  = (warp >> 2) * 64;   // 0 or 64
    const int wn0  = (warp & 3) * 32;    // 0,32,64,96

    float acc[4][4][4];
#pragma unroll
    for (int mt = 0; mt < 4; mt++)
#pragma unroll
        for (int nt = 0; nt < 4; nt++)
#pragma unroll
            for (int i = 0; i < 4; i++) acc[mt][nt][i] = 0.f;

    // loader: 4 threads per row, 16B each; 128 rows per operand = 2 passes
    const float* aptr[2];
    const float* bptr[2];
#pragma unroll
    for (int p = 0; p < 2; p++) {
        int cidx = tid + p * 256;        // 0..511
        int ra = row0 + (cidx >> 2);
        int rb = col0 + (cidx >> 2);
        aptr[p] = A  + (size_t)(ra < M ? ra : M - 1) * K + (cidx & 3) * 4;
        bptr[p] = Bw + (size_t)(rb < N ? rb : N - 1) * K + (cidx & 3) * 4;
    }

    auto issue = [&](int t) {
        const int s  = t & (STAGES - 1);
        const int k0 = t * 16;
        float* as = As + s * AST_;
        float* bs = Bs + s * BST_;
#pragma unroll
        for (int p = 0; p < 2; p++) {
            int cidx = tid + p * 256;
            cp16(as + (cidx >> 2) * 16 + (cidx & 3) * 4, aptr[p] + k0);
            cp16(bs + (cidx >> 2) * 16 + (cidx & 3) * 4, bptr[p] + k0);
        }
        cp_commit();
    };

    auto compute = [&](int s) {
        const float* as = As + s * AST_;
        const float* bs = Bs + s * BST_;
        float4 bv[4];
#pragma unroll
        for (int nt = 0; nt < 4; nt++)
            bv[nt] = *(const float4*)(bs + (wn0 + nt * 8 + lq) * 16 + lr * 4);
#pragma unroll
        for (int mt = 0; mt < 4; mt++) {
            float4 al = *(const float4*)(as + (wm0 + mt * 16 + lq) * 16 + lr * 4);
            float4 ah = *(const float4*)(as + (wm0 + mt * 16 + lq + 8) * 16 + lr * 4);
#pragma unroll
            for (int nt = 0; nt < 4; nt++)
                mma_tf32(acc[mt][nt], al.x, ah.x, al.y, ah.y, bv[nt].x, bv[nt].y);
#pragma unroll
            for (int nt = 0; nt < 4; nt++)
                mma_tf32(acc[mt][nt], al.z, ah.z, al.w, ah.w, bv[nt].z, bv[nt].w);
        }
    };

    const int T = K >> 4;
    issue(0); issue(1); issue(2);
    for (int t = 0; t < T; t++) {
        cp_wait<2>();
        __syncthreads();
        if (t + 3 < T) issue(t + 3);
        compute(t & (STAGES - 1));
    }

    // epilogue
#pragma unroll
    for (int mt = 0; mt < 4; mt++) {
#pragma unroll
        for (int half = 0; half < 2; half++) {
            int r = row0 + wm0 + mt * 16 + lq + half * 8;
            if (r >= M) continue;
            float* cr = C + (size_t)r * N;
#pragma unroll
            for (int nt = 0; nt < 4; nt++) {
                int c = col0 + wn0 + nt * 8 + 2 * lr;
#pragma unroll
                for (int u = 0; u < 2; u++) {
                    int cc = c + u;
                    if (cc >= N) continue;
                    float v = acc[mt][nt][half * 2 + u];
                    if (bias) v += bias[cc];
                    if (act)  v = rna_tf32(gelu_f(v));
                    cr[pout ? dperm(cc) : cc] = v;
                }
            }
        }
    }
}

// ---------------------------------------------------------------------------
// Fused attention: reads QKV natural, writes ATT permuted+rounded.
// ---------------------------------------------------------------------------
__global__ void k_attn(const float* __restrict__ QKV, float* __restrict__ OUT) {
    const int b = blockIdx.x >> 3;
    const int h = blockIdx.x & 7;
    extern __shared__ float smA[];
    float* Ks = smA;                      // [197*97]
    float* Vs = Ks + N_ * 97;             // [197*97]
    float* Ps = Vs + N_ * 97;             // [8*197]
    float* Qs = Ps + 8 * N_;              // [8*96]

    const float* base = QKV + (size_t)b * N_ * (3 * E_);
    const int tid = threadIdx.x;

    for (int idx = tid; idx < N_ * HD_; idx += 256) {
        int t = idx / HD_, d = idx - t * HD_;
        const float* rp = base + (size_t)t * (3 * E_) + h * HD_;
        Ks[t * 97 + d] = rp[E_ + d];
        Vs[t * 97 + d] = rp[2 * E_ + d];
    }
    __syncthreads();

    const int warp = tid >> 5, lane = tid & 31;
    int jcl[7];
#pragma unroll
    for (int jj = 0; jj < 7; jj++) {
        int j = jj * 32 + lane;
        jcl[jj] = (j < N_ ? j : N_ - 1) * 97;
    }

    const int p0 = dperm(lane), p1 = dperm(lane + 32), p2 = dperm(lane + 64);

    for (int q = warp; q < N_; q += 8) {
        const float* qp = base + (size_t)(q) * (3 * E_) + h * HD_;
        Qs[warp * HD_ + lane]      = qp[lane];
        Qs[warp * HD_ + lane + 32] = qp[lane + 32];
        Qs[warp * HD_ + lane + 64] = qp[lane + 64];
        __syncwarp();

        float s[7];
#pragma unroll
        for (int jj = 0; jj < 7; jj++) s[jj] = 0.f;
#pragma unroll 4
        for (int d = 0; d < HD_; d++) {
            float qd = Qs[warp * HD_ + d];
#pragma unroll
            for (int jj = 0; jj < 7; jj++) s[jj] += qd * Ks[jcl[jj] + d];
        }

        float mx = -1e30f;
#pragma unroll
        for (int jj = 0; jj < 7; jj++)
            if (jj * 32 + lane < N_) mx = fmaxf(mx, s[jj]);
#pragma unroll
        for (int o = 16; o > 0; o >>= 1)
            mx = fmaxf(mx, __shfl_xor_sync(0xffffffffu, mx, o));

        float sum = 0.f;
#pragma unroll
        for (int jj = 0; jj < 7; jj++) {
            float e = (jj * 32 + lane < N_) ? __expf(s[jj] - mx) : 0.f;
            s[jj] = e;
            sum += e;
        }
#pragma unroll
        for (int o = 16; o > 0; o >>= 1)
            sum += __shfl_xor_sync(0xffffffffu, sum, o);

        const float inv = SCALE_ / sum;   // softmax then *SCALE
#pragma unroll
        for (int jj = 0; jj < 7; jj++) {
            int j = jj * 32 + lane;
            if (j < N_) Ps[warp * N_ + j] = s[jj] * inv;
        }
        __syncwarp();

        float a0 = 0.f, a1 = 0.f, a2 = 0.f;
        for (int j = 0; j < N_; j++) {
            float p = Ps[warp * N_ + j];
            const float* vr = Vs + j * 97;
            a0 += p * vr[lane];
            a1 += p * vr[lane + 32];
            a2 += p * vr[lane + 64];
        }
        float* op = OUT + ((size_t)(b * N_ + q)) * E_ + h * HD_;
        op[p0] = rna_tf32(a0);
        op[p1] = rna_tf32(a1);
        op[p2] = rna_tf32(a2);
        __syncwarp();
    }
}

// ---------------------------------------------------------------------------
// add + LayerNorm on PERMUTED-layout buffers (params via dperm involution).
// ---------------------------------------------------------------------------
__global__ void k_add_ln(const float* __restrict__ Xin, const float* __restrict__ R,
                         float* __restrict__ Xout, const float* __restrict__ g,
                         const float* __restrict__ bt) {
    const int row = blockIdx.x;
    const int tid = threadIdx.x;
    const float* xr = Xin + (size_t)row * E_;
    const float* rr = R ? R + (size_t)row * E_ : nullptr;

    float v[3];
    float sum = 0.f, sq = 0.f;
#pragma unroll
    for (int c = 0; c < 3; c++) {
        int e = tid + c * 256;
        float t = xr[e] + (rr ? rr[e] : 0.f);
        v[c] = t;
        sum += t;
        sq += t * t;
    }
#pragma unroll
    for (int o = 16; o > 0; o >>= 1) {
        sum += __shfl_xor_sync(0xffffffffu, sum, o);
        sq  += __shfl_xor_sync(0xffffffffu, sq, o);
    }
    __shared__ float rs[8], rq[8];
    const int warp = tid >> 5, lane = tid & 31;
    if (lane == 0) { rs[warp] = sum; rq[warp] = sq; }
    __syncthreads();
    sum = 0.f; sq = 0.f;
#pragma unroll
    for (int w = 0; w < 8; w++) { sum += rs[w]; sq += rq[w]; }

    const float m   = sum * (1.f / E_);
    const float var = sq * (1.f / E_) - m * m;
    const float inv = rsqrtf(var + EPS_);
    float* orow = Xout + (size_t)row * E_;
#pragma unroll
    for (int c = 0; c < 3; c++) {
        int e  = tid + c * 256;
        int ne = dperm(e);
        orow[e] = rna_tf32((v[c] - m) * inv * g[ne] + bt[ne]);
    }
}

// ---------------------------------------------------------------------------
// mean pool over tokens (storage-order passthrough)
// ---------------------------------------------------------------------------
__global__ void k_pool(const float* __restrict__ X, float* __restrict__ P) {
    const int b = blockIdx.x / 3;
    const int e = (blockIdx.x % 3) * 256 + threadIdx.x;
    const float* xp = X + (size_t)b * N_ * E_ + e;
    float s = 0.f;
    for (int t = 0; t < N_; t++) s += xp[(size_t)t * E_];
    P[b * E_ + e] = s * (1.f / N_);
}

// ---------------------------------------------------------------------------
// host
// ---------------------------------------------------------------------------
extern "C" void kernel_launch(void* const* d_in, const int* in_sizes, int n_in,
                              void* d_out, int out_size) {
    const float* x      = (const float*)d_in[0];
    const float* conv_w = (const float*)d_in[1];
    const float* conv_b = (const float*)d_in[2];
    const float* cls    = (const float*)d_in[3];
    const float* pos    = (const float*)d_in[4];
    const float* qkv_w  = (const float*)d_in[5];
    const float* qkv_b  = (const float*)d_in[6];
    const float* proj_w = (const float*)d_in[7];
    const float* proj_b = (const float*)d_in[8];
    const float* ln1_g  = (const float*)d_in[9];
    const float* ln1_b  = (const float*)d_in[10];
    const float* mlp_w1 = (const float*)d_in[11];
    const float* mlp_b1 = (const float*)d_in[12];
    const float* mlp_w2 = (const float*)d_in[13];
    const float* mlp_b2 = (const float*)d_in[14];
    const float* ln2_g  = (const float*)d_in[15];
    const float* ln2_b  = (const float*)d_in[16];
    const float* hln_g  = (const float*)d_in[17];
    const float* hln_b  = (const float*)d_in[18];
    const float* head_w = (const float*)d_in[19];
    const float* head_b = (const float*)d_in[20];
    float* out = (float*)d_out;

    float* pool = nullptr;
    cudaGetSymbolAddress((void**)&pool, g_pool);
    float* X     = pool + oX;
    float* PATCH = pool + oPATCH;
    float* PE    = pool + oPE;
    float* QKV   = pool + oQKV;
    float* ATT   = pool + oATT;
    float* HID   = pool + oHID;
    float* T2    = pool + oT2;
    float* POOL  = pool + oPOOL;
    float* POOLN = pool + oPOOLN;
    float* WC    = pool + oWC;
    float* WQ    = pool + oWQ;
    float* WP    = pool + oWP;
    float* W1    = pool + oW1;
    float* W2    = pool + oW2;
    float* WH    = pool + oWH;

    const int attn_smem = (int)((2 * N_ * 97 + 8 * N_ + 8 * HD_) * sizeof(float));
    cudaFuncSetAttribute(k_attn, cudaFuncAttributeMaxDynamicSharedMemorySize, attn_smem);
    cudaFuncSetAttribute(k_mma_gemm, cudaFuncAttributeMaxDynamicSharedMemorySize, GSMEM);

    auto prepW = [&](const float* in, float* o, size_t n, int K) {
        int n4 = (int)(n / 4);
        k_round_perm<<<(n4 + 255) / 256, 256>>>(in, o, n4, K);
    };
    auto gemm = [&](const float* A, const float* Bw, const float* bias, float* Cst,
                    int M, int N, int K, int act, int pout) {
        dim3 g((N + 127) / 128, (M + 127) / 128);
        k_mma_gemm<<<g, 256, GSMEM>>>(A, Bw, bias, Cst, M, N, K, act, pout);
    };

    // launch order chosen so launch index 5 (ncu -s 5 -c 1) = layer-0 QKV GEMM
    prepW(conv_w, WC, (size_t)E_ * E_, E_);                       // 0
    k_im2col<<<(MP_ * E_ + 255) / 256, 256>>>(x, PATCH);          // 1
    gemm(PATCH, WC, conv_b, PE, MP_, E_, E_, 0, 0);               // 2
    k_assemble<<<(M_ * E_ + 255) / 256, 256>>>(PE, cls, pos, X);  // 3
    prepW(qkv_w, WQ, (size_t)L_ * 3 * E_ * E_, E_);               // 4

    for (int l = 0; l < L_; l++) {
        const float* qw  = WQ + (size_t)l * 3 * E_ * E_;
        const float* qb  = qkv_b  + (size_t)l * 3 * E_;
        const float* pw  = WP + (size_t)l * E_ * E_;
        const float* pb  = proj_b + (size_t)l * E_;
        const float* g1g = ln1_g  + (size_t)l * E_;
        const float* g1b = ln1_b  + (size_t)l * E_;
        const float* w1  = W1 + (size_t)l * FF_ * E_;
        const float* b1  = mlp_b1 + (size_t)l * FF_;
        const float* w2  = W2 + (size_t)l * E_ * FF_;
        const float* b2  = mlp_b2 + (size_t)l * E_;
        const float* g2g = ln2_g  + (size_t)l * E_;
        const float* g2b = ln2_b  + (size_t)l * E_;

        gemm(X, qw, qb, QKV, M_, 3 * E_, E_, 0, 0);        // launch 5 on l==0
        k_attn<<<B_ * H_, 256, attn_smem>>>(QKV, ATT);
        if (l == 0) prepW(proj_w, WP, (size_t)L_ * E_ * E_, E_);
        gemm(ATT, pw, pb, T2, M_, E_, E_, 0, 1);
        k_add_ln<<<M_, 256>>>(X, T2, X, g1g, g1b);
        if (l == 0) prepW(mlp_w1, W1, (size_t)L_ * FF_ * E_, E_);
        gemm(X, w1, b1, HID, M_, FF_, E_, 1, 1);
        if (l == 0) prepW(mlp_w2, W2, (size_t)L_ * E_ * FF_, FF_);
        gemm(HID, w2, b2, T2, M_, E_, FF_, 0, 1);
        k_add_ln<<<M_, 256>>>(X, T2, X, g2g, g2b);
    }

    // classifier head
    prepW(head_w, WH, (size_t)NC_ * E_, E_);
    k_pool<<<B_ * 3, 256>>>(X, POOL);
    k_add_ln<<<B_, 256>>>(POOL, nullptr, POOLN, hln_g, hln_b);
    gemm(POOLN, WH, head_b, out, B_, NC_, E_, 0, 0);
}